// round 1
// baseline (speedup 1.0000x reference)
#include <cuda_runtime.h>
#include <math.h>
#include <stdint.h>

typedef unsigned long long ull;

#define NBATCH 1024
#define SEQL   200
#define DIM    256
#define NCAPS  8

// ---------------- device scratch (no allocations allowed) ----------------
__device__ float g_mapped[(size_t)NBATCH * SEQL * DIM];   // 209.7 MB
__device__ float g_logits[NCAPS * SEQL];                  // 6.4 KB
__device__ float g_part[(size_t)NBATCH * NCAPS * SEQL];   // 6.55 MB per-batch delta partials

// ---------------- f32x2 helpers (Blackwell packed fp32) -------------------
__device__ __forceinline__ ull ffma2(ull a, ull b, ull c) {
    ull d;
    asm("fma.rn.f32x2 %0, %1, %2, %3;" : "=l"(d) : "l"(a), "l"(b), "l"(c));
    return d;
}
__device__ __forceinline__ ull dup2(float x) {
    ull d;
    asm("mov.b64 %0, {%1, %1};" : "=l"(d) : "f"(x));
    return d;
}
__device__ __forceinline__ float2 unpack2(ull a) {
    float2 f;
    asm("mov.b64 {%0, %1}, %2;" : "=f"(f.x), "=f"(f.y) : "l"(a));
    return f;
}

// ---------------- init: copy routing logits into mutable buffer ----------
__global__ void k_init(const float* __restrict__ rlog) {
    int i = blockIdx.x * blockDim.x + threadIdx.x;
    if (i < NCAPS * SEQL) g_logits[i] = rlog[i];
}

// ---------------- GEMM: g_mapped = emb[204800,256] @ W[256,256] ----------
// 64x64 tile, BK=16, 256 threads, 4x4 micro-tile, f32x2 math.
// A operand stored duplicated in SMEM so LDS.128 yields {a,a} pairs directly.
__global__ __launch_bounds__(256) void k_gemm(const float* __restrict__ A,
                                              const float* __restrict__ W) {
    constexpr int BM = 64, BN = 64, BK = 16;
    __shared__ __align__(16) float As2[BK][2 * BM];  // duplicated along m
    __shared__ __align__(16) float Bs[BK][BN];

    int tid = threadIdx.x;
    int tx = tid & 15, ty = tid >> 4;
    size_t m0 = (size_t)blockIdx.y * BM;
    int n0 = blockIdx.x * BN;

    int la_r = tid >> 2;           // 0..63 (m within tile)
    int la_c = (tid & 3) * 4;      // 0,4,8,12 (k within tile)
    int lb_r = tid >> 4;           // 0..15 (k within tile)
    int lb_c = (tid & 15) * 4;     // 0..60 (n within tile)

    const float* Aload = A + (m0 + la_r) * DIM + la_c;
    const float* Wload = W + (size_t)lb_r * DIM + n0 + lb_c;

    ull acc[4][2];
#pragma unroll
    for (int i = 0; i < 4; i++) { acc[i][0] = 0ULL; acc[i][1] = 0ULL; }

    for (int k0 = 0; k0 < DIM; k0 += BK) {
        float4 av = *(const float4*)(Aload + k0);
        float4 bv = *(const float4*)(Wload + (size_t)k0 * DIM);
        __syncthreads();
        As2[la_c + 0][2 * la_r] = av.x; As2[la_c + 0][2 * la_r + 1] = av.x;
        As2[la_c + 1][2 * la_r] = av.y; As2[la_c + 1][2 * la_r + 1] = av.y;
        As2[la_c + 2][2 * la_r] = av.z; As2[la_c + 2][2 * la_r + 1] = av.z;
        As2[la_c + 3][2 * la_r] = av.w; As2[la_c + 3][2 * la_r + 1] = av.w;
        *(float4*)&Bs[lb_r][lb_c] = bv;
        __syncthreads();
#pragma unroll
        for (int kk = 0; kk < BK; kk++) {
            ulonglong2 a01 = *(const ulonglong2*)&As2[kk][8 * ty];
            ulonglong2 a23 = *(const ulonglong2*)&As2[kk][8 * ty + 4];
            ulonglong2 b   = *(const ulonglong2*)&Bs[kk][4 * tx];
            acc[0][0] = ffma2(a01.x, b.x, acc[0][0]);
            acc[0][1] = ffma2(a01.x, b.y, acc[0][1]);
            acc[1][0] = ffma2(a01.y, b.x, acc[1][0]);
            acc[1][1] = ffma2(a01.y, b.y, acc[1][1]);
            acc[2][0] = ffma2(a23.x, b.x, acc[2][0]);
            acc[2][1] = ffma2(a23.x, b.y, acc[2][1]);
            acc[3][0] = ffma2(a23.y, b.x, acc[3][0]);
            acc[3][1] = ffma2(a23.y, b.y, acc[3][1]);
        }
    }

    float* Cp = g_mapped + (m0 + (size_t)ty * 4) * DIM + n0 + tx * 4;
#pragma unroll
    for (int i = 0; i < 4; i++) {
        float2 lo = unpack2(acc[i][0]);
        float2 hi = unpack2(acc[i][1]);
        float4 v = make_float4(lo.x, lo.y, hi.x, hi.y);
        *(float4*)(Cp + (size_t)i * DIM) = v;
    }
}

// ---------------- fused routing iteration: CTA per batch ------------------
// SMEM layout (floats):
#define SM_W_OFF    (SEQL * DIM)                 // 51200
#define SM_CAPS_OFF (SM_W_OFF + SEQL * NCAPS)    // 52800
#define SM_RED_OFF  (SM_CAPS_OFF + NCAPS * DIM)  // 54848
#define SM_SC_OFF   (SM_RED_OFF + 64)            // 54912
#define SM_FLOATS   (SM_SC_OFF + 8)              // 54920
#define SMEM_BYTES  (SM_FLOATS * 4)              // 219680 B

__global__ __launch_bounds__(256) void k_capsule(const int* __restrict__ seq_len,
                                                 float* __restrict__ out,
                                                 int do_delta) {
    extern __shared__ __align__(16) float sm[];
    float* sm_m    = sm;                 // [200][256] mapped_b
    float* sm_w    = sm + SM_W_OFF;      // [200][8]   softmax weights (l-major)
    float* sm_caps = sm + SM_CAPS_OFF;   // [8][256]   squashed capsules
    float* sm_red  = sm + SM_RED_OFF;    // [8][8]     per-warp partial norms
    float* sm_sc   = sm + SM_SC_OFF;     // [8]        squash scales

    int b = blockIdx.x;
    int tid = threadIdx.x;
    int warp = tid >> 5, lane = tid & 31;
    int seq = seq_len[b];

    // ---- load mapped_b into SMEM (coalesced float4) ----
    {
        const float4* src = (const float4*)(g_mapped + (size_t)b * (SEQL * DIM));
        float4* dst = (float4*)sm_m;
#pragma unroll
        for (int i = 0; i < (SEQL * DIM / 4) / 256; i++)
            dst[i * 256 + tid] = src[i * 256 + tid];
    }

    // ---- masked softmax over l for capsule k = warp ----
    {
        int k = warp;
        float vals[7];
        float mx = -INFINITY;
#pragma unroll
        for (int j = 0; j < 7; j++) {
            int l = lane + 32 * j;
            float v = (l < seq) ? g_logits[k * SEQL + l] : -INFINITY;
            vals[j] = v;
            mx = fmaxf(mx, v);
        }
#pragma unroll
        for (int off = 16; off; off >>= 1)
            mx = fmaxf(mx, __shfl_xor_sync(0xffffffffu, mx, off));
        float s = 0.f;
#pragma unroll
        for (int j = 0; j < 7; j++) {
            float e = expf(vals[j] - mx);   // expf(-inf)=0 for masked
            vals[j] = e;
            s += e;
        }
#pragma unroll
        for (int off = 16; off; off >>= 1)
            s += __shfl_xor_sync(0xffffffffu, s, off);
        float inv = 1.f / s;
#pragma unroll
        for (int j = 0; j < 7; j++) {
            int l = lane + 32 * j;
            if (l < SEQL) sm_w[l * NCAPS + k] = vals[j] * inv;
        }
    }
    __syncthreads();

    // ---- Z[k][o] = sum_l w[k][l] * m[l][o]; thread owns o=tid, f32x2 over k ----
    int o = tid;
    ull z2[4] = {0ULL, 0ULL, 0ULL, 0ULL};
    for (int l = 0; l < seq; l++) {
        float m = sm_m[l * DIM + o];
        ull md = dup2(m);
        ulonglong2 wa = *(const ulonglong2*)&sm_w[l * NCAPS];
        ulonglong2 wb = *(const ulonglong2*)&sm_w[l * NCAPS + 4];
        z2[0] = ffma2(md, wa.x, z2[0]);
        z2[1] = ffma2(md, wa.y, z2[1]);
        z2[2] = ffma2(md, wb.x, z2[2]);
        z2[3] = ffma2(md, wb.y, z2[3]);
    }
    float z[8];
    {
        float2 f;
        f = unpack2(z2[0]); z[0] = f.x; z[1] = f.y;
        f = unpack2(z2[1]); z[2] = f.x; z[3] = f.y;
        f = unpack2(z2[2]); z[4] = f.x; z[5] = f.y;
        f = unpack2(z2[3]); z[6] = f.x; z[7] = f.y;
    }

    // ---- squash: sq_k = sum_o z^2 (warp reduce + cross-warp via SMEM) ----
    {
        float zs[8];
#pragma unroll
        for (int k = 0; k < 8; k++) zs[k] = z[k] * z[k];
#pragma unroll
        for (int off = 16; off; off >>= 1)
#pragma unroll
            for (int k = 0; k < 8; k++)
                zs[k] += __shfl_xor_sync(0xffffffffu, zs[k], off);
        if (lane == 0) {
#pragma unroll
            for (int k = 0; k < 8; k++) sm_red[k * 8 + warp] = zs[k];
        }
    }
    __syncthreads();
    if (tid < 8) {
        float sq = 0.f;
#pragma unroll
        for (int w = 0; w < 8; w++) sq += sm_red[tid * 8 + w];
        float sc = sq / (1.f + sq) / sqrtf(sq + 1e-8f);
        sm_sc[tid] = sc;
    }
    __syncthreads();

    // ---- capsules = scale * Z; write to out and SMEM ----
#pragma unroll
    for (int k = 0; k < 8; k++) {
        float c = sm_sc[k] * z[k];
        sm_caps[k * DIM + o] = c;
        out[((size_t)b * NCAPS + k) * DIM + o] = c;
    }

    // ---- delta[k][l] = sum_o caps[k][o] * m[l][o]  (per-batch partial) ----
    if (do_delta) {
        __syncthreads();
        float4 c0[8], c1[8];
#pragma unroll
        for (int k = 0; k < 8; k++) {
            c0[k] = *(const float4*)&sm_caps[k * DIM + lane * 8];
            c1[k] = *(const float4*)&sm_caps[k * DIM + lane * 8 + 4];
        }
        for (int l = warp; l < SEQL; l += 8) {
            float4 m0 = *(const float4*)&sm_m[l * DIM + lane * 8];
            float4 m1 = *(const float4*)&sm_m[l * DIM + lane * 8 + 4];
            float p[8];
#pragma unroll
            for (int k = 0; k < 8; k++) {
                p[k] = c0[k].x * m0.x + c0[k].y * m0.y + c0[k].z * m0.z + c0[k].w * m0.w
                     + c1[k].x * m1.x + c1[k].y * m1.y + c1[k].z * m1.z + c1[k].w * m1.w;
            }
#pragma unroll
            for (int off = 16; off; off >>= 1)
#pragma unroll
                for (int k = 0; k < 8; k++)
                    p[k] += __shfl_xor_sync(0xffffffffu, p[k], off);
            if (lane == 0) {
                float* dp = g_part + (size_t)b * (NCAPS * SEQL) + l;
#pragma unroll
                for (int k = 0; k < 8; k++) dp[k * SEQL] = p[k];
            }
        }
    }
}

// ---------------- deterministic batch-reduce of delta into logits --------
__global__ __launch_bounds__(256) void k_update() {
    __shared__ float red[256];
    int i = blockIdx.x;  // 0..1599 (k*200+l)
    float s = 0.f;
    for (int b = threadIdx.x; b < NBATCH; b += 256)
        s += g_part[(size_t)b * (NCAPS * SEQL) + i];
    red[threadIdx.x] = s;
    __syncthreads();
#pragma unroll
    for (int st = 128; st; st >>= 1) {
        if (threadIdx.x < st) red[threadIdx.x] += red[threadIdx.x + st];
        __syncthreads();
    }
    if (threadIdx.x == 0) g_logits[i] += red[0];
}

// ---------------- launch --------------------------------------------------
extern "C" void kernel_launch(void* const* d_in, const int* in_sizes, int n_in,
                              void* d_out, int out_size) {
    const float* emb  = (const float*)d_in[0];   // [1024, 200, 256]
    const int*   seq  = (const int*)d_in[1];     // [1024, 1]
    const float* rlog = (const float*)d_in[2];   // [1, 8, 200]
    const float* W    = (const float*)d_in[3];   // [256, 256]
    float* out = (float*)d_out;                  // [1024, 8, 256]

    cudaFuncSetAttribute(k_capsule, cudaFuncAttributeMaxDynamicSharedMemorySize,
                         SMEM_BYTES);

    k_init<<<(NCAPS * SEQL + 255) / 256, 256>>>(rlog);
    k_gemm<<<dim3(DIM / 64, (NBATCH * SEQL) / 64), 256>>>(emb, W);

    for (int it = 0; it < 3; it++) {
        k_capsule<<<NBATCH, 256, SMEM_BYTES>>>(seq, out, (it < 2) ? 1 : 0);
        if (it < 2) k_update<<<NCAPS * SEQL, 256>>>();
    }
}

// round 3
// speedup vs baseline: 2.3541x; 2.3541x over previous
#include <cuda_runtime.h>
#include <cuda_bf16.h>
#include <math.h>
#include <stdint.h>

typedef unsigned long long ull;

#define NBATCH 1024
#define SEQL   200
#define DIM    256
#define NCAPS  8

// tcgen05 is arch-SPECIFIC: only legal on sm_103a/sm_100a compilation variants.
// The harness also runs a generic compute_103 PTX pass; give it a fallback.
#if !defined(__CUDA_ARCH__) || defined(__CUDA_ARCH_FEAT_SM103_ALL) || \
    defined(__CUDA_ARCH_FEAT_SM100_ALL) || defined(__CUDA_ARCH_FEAT_SM101_ALL)
#define TC_OK 1
#else
#define TC_OK 0
#endif

// ---------------- device scratch (no allocations allowed) ----------------
__device__ float g_mapped[(size_t)NBATCH * SEQL * DIM];   // 209.7 MB
__device__ float g_logits[NCAPS * SEQL];                  // 6.4 KB
__device__ float g_part[(size_t)NBATCH * NCAPS * SEQL];   // 6.55 MB
__device__ __nv_bfloat16 g_WhT[DIM * DIM];                // W^T hi split, [n][k]
__device__ __nv_bfloat16 g_WlT[DIM * DIM];                // W^T lo split, [n][k]

// ---------------- f32x2 helpers ------------------------------------------
__device__ __forceinline__ ull ffma2(ull a, ull b, ull c) {
    ull d;
    asm("fma.rn.f32x2 %0, %1, %2, %3;" : "=l"(d) : "l"(a), "l"(b), "l"(c));
    return d;
}
__device__ __forceinline__ ull dup2(float x) {
    ull d;
    asm("mov.b64 %0, {%1, %1};" : "=l"(d) : "f"(x));
    return d;
}
__device__ __forceinline__ float2 unpack2(ull a) {
    float2 f;
    asm("mov.b64 {%0, %1}, %2;" : "=f"(f.x), "=f"(f.y) : "l"(a));
    return f;
}

// ---------------- tcgen05 / mbarrier PTX helpers -------------------------
__device__ __forceinline__ uint32_t smem_u32(const void* p) {
    uint32_t a;
    asm("{ .reg .u64 t; cvta.to.shared.u64 t, %1; cvt.u32.u64 %0, t; }"
        : "=r"(a) : "l"(p));
    return a;
}

#if TC_OK
__device__ __forceinline__ uint32_t elect1() {
    uint32_t p;
    asm volatile("{ .reg .pred p; elect.sync _|p, 0xFFFFFFFF; selp.b32 %0,1,0,p; }"
                 : "=r"(p));
    return p;
}
__device__ __forceinline__ void mma_f16_ss(uint32_t d, uint64_t a, uint64_t b,
                                           uint32_t id, uint32_t en) {
    asm volatile(
        "{\n\t.reg .pred p;\n\tsetp.ne.u32 p, %5, 0;\n\t"
        "tcgen05.mma.cta_group::1.kind::f16 [%0], %1, %2, %3, {%4,%4,%4,%4}, p;\n\t}"
        :: "r"(d), "l"(a), "l"(b), "r"(id), "r"(0u), "r"(en) : "memory");
}
__device__ __forceinline__ void mbar_wait(uint32_t a, uint32_t par) {
    asm volatile(
        "{\n\t.reg .pred P;\n"
        "W%=:\n\t"
        "mbarrier.try_wait.parity.acquire.cta.shared::cta.b64 P, [%0], %1, 0x989680;\n\t"
        "@P bra D%=;\n\t"
        "bra W%=;\n"
        "D%=:\n\t}" :: "r"(a), "r"(par) : "memory");
}
#define LDTM_X32(r, addr) \
    asm volatile( \
        "tcgen05.ld.sync.aligned.32x32b.x32.b32 " \
        "{%0,%1,%2,%3,%4,%5,%6,%7,%8,%9,%10,%11,%12,%13,%14,%15," \
        "%16,%17,%18,%19,%20,%21,%22,%23,%24,%25,%26,%27,%28,%29,%30,%31}, [%32];" \
        : "=r"((r)[0]),"=r"((r)[1]),"=r"((r)[2]),"=r"((r)[3]), \
          "=r"((r)[4]),"=r"((r)[5]),"=r"((r)[6]),"=r"((r)[7]), \
          "=r"((r)[8]),"=r"((r)[9]),"=r"((r)[10]),"=r"((r)[11]), \
          "=r"((r)[12]),"=r"((r)[13]),"=r"((r)[14]),"=r"((r)[15]), \
          "=r"((r)[16]),"=r"((r)[17]),"=r"((r)[18]),"=r"((r)[19]), \
          "=r"((r)[20]),"=r"((r)[21]),"=r"((r)[22]),"=r"((r)[23]), \
          "=r"((r)[24]),"=r"((r)[25]),"=r"((r)[26]),"=r"((r)[27]), \
          "=r"((r)[28]),"=r"((r)[29]),"=r"((r)[30]),"=r"((r)[31]) \
        : "r"(addr))
#endif  // TC_OK

// ---------------- init kernels -------------------------------------------
__global__ void k_init(const float* __restrict__ rlog) {
    int i = blockIdx.x * blockDim.x + threadIdx.x;
    if (i < NCAPS * SEQL) g_logits[i] = rlog[i];
}

// split + transpose W: g_W*T[n][k] = split(W[k][n])
__global__ void k_convW(const float* __restrict__ W) {
    int k = blockIdx.x;
    int n = threadIdx.x;
    float v = W[k * DIM + n];
    __nv_bfloat16 h = __float2bfloat16(v);
    float r = v - __bfloat162float(h);
    g_WhT[n * DIM + k] = h;
    g_WlT[n * DIM + k] = __float2bfloat16(r);
}

// ---------------- tensor-core GEMM: g_mapped = A @ W ----------------------
// bf16-split 3-product, M=128 per CTA, N=256, K chunks of 64, SW128 SMEM.
#define OFF_AH 1024
#define OFF_AL 17408
#define OFF_BH 33792
#define OFF_BL 66560
#define GSM_BYTES 99328

__global__ __launch_bounds__(256) void k_gemm_tc(const float* __restrict__ A,
                                                 const float* __restrict__ W) {
#if TC_OK
    extern __shared__ __align__(16) float sm[];
    char* sb = (char*)sm;
    uint32_t sbase = smem_u32(sm);
    int tid = threadIdx.x, wid = tid >> 5;
    size_t m0 = (size_t)blockIdx.x * 128;

    if (wid == 0) {
        asm volatile("tcgen05.alloc.cta_group::1.sync.aligned.shared::cta.b32 [%0], %1;"
                     :: "r"(sbase), "r"(256u) : "memory");
        asm volatile("tcgen05.relinquish_alloc_permit.cta_group::1.sync.aligned;");
    }
    __syncthreads();
    uint32_t tb;
    asm volatile("ld.shared.b32 %0, [%1];" : "=r"(tb) : "r"(sbase));

    if (tid == 0)
        asm volatile("mbarrier.init.shared.b64 [%0], %1;"
                     :: "r"(sbase + 8), "r"(1u) : "memory");
    __syncthreads();

    const uint64_t DB = (2ULL << 61) | (1ULL << 46) | (64ULL << 32) | (1ULL << 16);
    uint64_t dAh = DB | (((uint64_t)(sbase + OFF_AH) >> 4) & 0x3FFF);
    uint64_t dAl = DB | (((uint64_t)(sbase + OFF_AL) >> 4) & 0x3FFF);
    uint64_t dBh = DB | (((uint64_t)(sbase + OFF_BH) >> 4) & 0x3FFF);
    uint64_t dBl = DB | (((uint64_t)(sbase + OFF_BL) >> 4) & 0x3FFF);
    // idesc: F32 acc, BF16 a/b, N=256, M=128
    const uint32_t idesc = (1u << 4) | (1u << 7) | (1u << 10) |
                           ((DIM / 8) << 17) | ((128 / 16) << 24);

    uint32_t first = 0;  // en = first != 0
    for (int c = 0; c < 4; c++) {
        int k0 = c * 64;
        // --- A chunk: 128 rows x 64 fp32 -> split bf16, swizzled STS ---
#pragma unroll
        for (int i = 0; i < 8; i++) {
            int idx = tid + i * 256;
            int r = idx >> 4, c4 = idx & 15;
            float4 f = *(const float4*)(A + (m0 + r) * DIM + k0 + c4 * 4);
            __nv_bfloat16 h0 = __float2bfloat16(f.x), h1 = __float2bfloat16(f.y),
                          h2 = __float2bfloat16(f.z), h3 = __float2bfloat16(f.w);
            float l0 = f.x - __bfloat162float(h0), l1 = f.y - __bfloat162float(h1),
                  l2 = f.z - __bfloat162float(h2), l3 = f.w - __bfloat162float(h3);
            uint32_t off = r * 128 + c4 * 8;
            uint32_t sw = off ^ ((off >> 3) & 0x70);
            uint2 uh, ulv;
            uh.x = ((uint32_t)__bfloat16_as_ushort(h1) << 16) | __bfloat16_as_ushort(h0);
            uh.y = ((uint32_t)__bfloat16_as_ushort(h3) << 16) | __bfloat16_as_ushort(h2);
            __nv_bfloat16 q0 = __float2bfloat16(l0), q1 = __float2bfloat16(l1),
                          q2 = __float2bfloat16(l2), q3 = __float2bfloat16(l3);
            ulv.x = ((uint32_t)__bfloat16_as_ushort(q1) << 16) | __bfloat16_as_ushort(q0);
            ulv.y = ((uint32_t)__bfloat16_as_ushort(q3) << 16) | __bfloat16_as_ushort(q2);
            *(uint2*)(sb + OFF_AH + sw) = uh;
            *(uint2*)(sb + OFF_AL + sw) = ulv;
        }
        // --- B chunk: 256 rows x 64 bf16 (both splits), swizzled STS ---
#pragma unroll
        for (int i = 0; i < 8; i++) {
            int idx = tid + i * 256;
            int r = idx >> 3, cc = idx & 7;
            uint32_t off = r * 128 + cc * 16;
            uint32_t sw = off ^ ((off >> 3) & 0x70);
            uint4 vh = *(const uint4*)((const char*)g_WhT + r * 512 + k0 * 2 + cc * 16);
            uint4 vl = *(const uint4*)((const char*)g_WlT + r * 512 + k0 * 2 + cc * 16);
            *(uint4*)(sb + OFF_BH + sw) = vh;
            *(uint4*)(sb + OFF_BL + sw) = vl;
        }
        __syncthreads();
        if (wid == 0) {
            asm volatile("fence.proxy.async.shared::cta;" ::: "memory");
            if (elect1()) {
#pragma unroll
                for (int s = 0; s < 4; s++) {
                    mma_f16_ss(tb, dAh + s * 2, dBh + s * 2, idesc, first);
                    first = 1;
                    mma_f16_ss(tb, dAh + s * 2, dBl + s * 2, idesc, 1);
                    mma_f16_ss(tb, dAl + s * 2, dBh + s * 2, idesc, 1);
                }
                asm volatile(
                    "tcgen05.commit.cta_group::1.mbarrier::arrive::one.shared::cluster.b64 [%0];"
                    :: "r"(sbase + 8) : "memory");
            }
        }
        mbar_wait(sbase + 8, (uint32_t)(c & 1));
    }

    asm volatile("tcgen05.fence::after_thread_sync;" ::: "memory");
    if (tid < 128) {
        float* Crow = g_mapped + (m0 + tid) * DIM;
#pragma unroll
        for (int j = 0; j < 8; j++) {
            uint32_t r[32];
            LDTM_X32(r, tb + j * 32);
            asm volatile("tcgen05.wait::ld.sync.aligned;" ::: "memory");
#pragma unroll
            for (int q = 0; q < 8; q++) {
                float4 v = make_float4(__uint_as_float(r[q * 4 + 0]),
                                       __uint_as_float(r[q * 4 + 1]),
                                       __uint_as_float(r[q * 4 + 2]),
                                       __uint_as_float(r[q * 4 + 3]));
                *(float4*)(Crow + j * 32 + q * 4) = v;
            }
        }
    }
    __syncthreads();
    if (wid == 0) {
        asm volatile("tcgen05.dealloc.cta_group::1.sync.aligned.b32 %0, %1;"
                     :: "r"(tb), "r"(256u));
    }
#else
    // Generic-PTX fallback (never executed on GB300; sm_103a cubin is loaded).
    // Simple but correct: each thread computes 128 outputs of the 128x256 tile.
    size_t m0 = (size_t)blockIdx.x * 128;
    int tid = threadIdx.x;
    for (int e = tid; e < 128 * 256; e += 256) {
        int r = e >> 8, n = e & 255;
        float acc = 0.f;
        for (int k = 0; k < DIM; k++)
            acc += A[(m0 + r) * DIM + k] * W[k * DIM + n];
        g_mapped[(m0 + r) * DIM + n] = acc;
    }
#endif
}

// ---------------- fused routing iteration: CTA per batch ------------------
#define SM_W_OFF    (SEQL * DIM)
#define SM_CAPS_OFF (SM_W_OFF + SEQL * NCAPS)
#define SM_RED_OFF  (SM_CAPS_OFF + NCAPS * DIM)
#define SM_SC_OFF   (SM_RED_OFF + 64)
#define SM_FLOATS   (SM_SC_OFF + 8)
#define SMEM_BYTES  (SM_FLOATS * 4)

__global__ __launch_bounds__(256) void k_capsule(const int* __restrict__ seq_len,
                                                 float* __restrict__ out,
                                                 int do_delta) {
    extern __shared__ __align__(16) float sm[];
    float* sm_m    = sm;
    float* sm_w    = sm + SM_W_OFF;
    float* sm_caps = sm + SM_CAPS_OFF;
    float* sm_red  = sm + SM_RED_OFF;
    float* sm_sc   = sm + SM_SC_OFF;

    int b = blockIdx.x;
    int tid = threadIdx.x;
    int warp = tid >> 5, lane = tid & 31;
    int seq = seq_len[b];

    {
        const float4* src = (const float4*)(g_mapped + (size_t)b * (SEQL * DIM));
        float4* dst = (float4*)sm_m;
#pragma unroll
        for (int i = 0; i < (SEQL * DIM / 4) / 256; i++)
            dst[i * 256 + tid] = src[i * 256 + tid];
    }

    {
        int k = warp;
        float vals[7];
        float mx = -INFINITY;
#pragma unroll
        for (int j = 0; j < 7; j++) {
            int l = lane + 32 * j;
            float v = (l < seq) ? g_logits[k * SEQL + l] : -INFINITY;
            vals[j] = v;
            mx = fmaxf(mx, v);
        }
#pragma unroll
        for (int off = 16; off; off >>= 1)
            mx = fmaxf(mx, __shfl_xor_sync(0xffffffffu, mx, off));
        float s = 0.f;
#pragma unroll
        for (int j = 0; j < 7; j++) {
            float e = expf(vals[j] - mx);
            vals[j] = e;
            s += e;
        }
#pragma unroll
        for (int off = 16; off; off >>= 1)
            s += __shfl_xor_sync(0xffffffffu, s, off);
        float inv = 1.f / s;
#pragma unroll
        for (int j = 0; j < 7; j++) {
            int l = lane + 32 * j;
            if (l < SEQL) sm_w[l * NCAPS + k] = vals[j] * inv;
        }
    }
    __syncthreads();

    int o = tid;
    ull z2[4] = {0ULL, 0ULL, 0ULL, 0ULL};
    for (int l = 0; l < seq; l++) {
        float m = sm_m[l * DIM + o];
        ull md = dup2(m);
        ulonglong2 wa = *(const ulonglong2*)&sm_w[l * NCAPS];
        ulonglong2 wb = *(const ulonglong2*)&sm_w[l * NCAPS + 4];
        z2[0] = ffma2(md, wa.x, z2[0]);
        z2[1] = ffma2(md, wa.y, z2[1]);
        z2[2] = ffma2(md, wb.x, z2[2]);
        z2[3] = ffma2(md, wb.y, z2[3]);
    }
    float z[8];
    {
        float2 f;
        f = unpack2(z2[0]); z[0] = f.x; z[1] = f.y;
        f = unpack2(z2[1]); z[2] = f.x; z[3] = f.y;
        f = unpack2(z2[2]); z[4] = f.x; z[5] = f.y;
        f = unpack2(z2[3]); z[6] = f.x; z[7] = f.y;
    }

    {
        float zs[8];
#pragma unroll
        for (int k = 0; k < 8; k++) zs[k] = z[k] * z[k];
#pragma unroll
        for (int off = 16; off; off >>= 1)
#pragma unroll
            for (int k = 0; k < 8; k++)
                zs[k] += __shfl_xor_sync(0xffffffffu, zs[k], off);
        if (lane == 0) {
#pragma unroll
            for (int k = 0; k < 8; k++) sm_red[k * 8 + warp] = zs[k];
        }
    }
    __syncthreads();
    if (tid < 8) {
        float sq = 0.f;
#pragma unroll
        for (int w = 0; w < 8; w++) sq += sm_red[tid * 8 + w];
        sm_sc[tid] = sq / (1.f + sq) / sqrtf(sq + 1e-8f);
    }
    __syncthreads();

#pragma unroll
    for (int k = 0; k < 8; k++) {
        float c = sm_sc[k] * z[k];
        sm_caps[k * DIM + o] = c;
        out[((size_t)b * NCAPS + k) * DIM + o] = c;
    }

    if (do_delta) {
        __syncthreads();
        float4 c0[8], c1[8];
#pragma unroll
        for (int k = 0; k < 8; k++) {
            c0[k] = *(const float4*)&sm_caps[k * DIM + lane * 8];
            c1[k] = *(const float4*)&sm_caps[k * DIM + lane * 8 + 4];
        }
        for (int l = warp; l < SEQL; l += 8) {
            float4 m0 = *(const float4*)&sm_m[l * DIM + lane * 8];
            float4 m1 = *(const float4*)&sm_m[l * DIM + lane * 8 + 4];
            float p[8];
#pragma unroll
            for (int k = 0; k < 8; k++) {
                p[k] = c0[k].x * m0.x + c0[k].y * m0.y + c0[k].z * m0.z + c0[k].w * m0.w
                     + c1[k].x * m1.x + c1[k].y * m1.y + c1[k].z * m1.z + c1[k].w * m1.w;
            }
#pragma unroll
            for (int off = 16; off; off >>= 1)
#pragma unroll
                for (int k = 0; k < 8; k++)
                    p[k] += __shfl_xor_sync(0xffffffffu, p[k], off);
            if (lane == 0) {
                float* dp = g_part + (size_t)b * (NCAPS * SEQL) + l;
#pragma unroll
                for (int k = 0; k < 8; k++) dp[k * SEQL] = p[k];
            }
        }
    }
}

// ---------------- deterministic batch-reduce of delta into logits --------
__global__ __launch_bounds__(256) void k_update() {
    __shared__ float red[256];
    int i = blockIdx.x;
    float s = 0.f;
    for (int b = threadIdx.x; b < NBATCH; b += 256)
        s += g_part[(size_t)b * (NCAPS * SEQL) + i];
    red[threadIdx.x] = s;
    __syncthreads();
#pragma unroll
    for (int st = 128; st; st >>= 1) {
        if (threadIdx.x < st) red[threadIdx.x] += red[threadIdx.x + st];
        __syncthreads();
    }
    if (threadIdx.x == 0) g_logits[i] += red[0];
}

// ---------------- launch --------------------------------------------------
extern "C" void kernel_launch(void* const* d_in, const int* in_sizes, int n_in,
                              void* d_out, int out_size) {
    const float* emb  = (const float*)d_in[0];
    const int*   seq  = (const int*)d_in[1];
    const float* rlog = (const float*)d_in[2];
    const float* W    = (const float*)d_in[3];
    float* out = (float*)d_out;

    cudaFuncSetAttribute(k_capsule, cudaFuncAttributeMaxDynamicSharedMemorySize,
                         SMEM_BYTES);
    cudaFuncSetAttribute(k_gemm_tc, cudaFuncAttributeMaxDynamicSharedMemorySize,
                         GSM_BYTES);

    k_init<<<(NCAPS * SEQL + 255) / 256, 256>>>(rlog);
    k_convW<<<DIM, DIM>>>(W);
    k_gemm_tc<<<(NBATCH * SEQL) / 128, 256, GSM_BYTES>>>(emb, W);

    for (int it = 0; it < 3; it++) {
        k_capsule<<<NBATCH, 256, SMEM_BYTES>>>(seq, out, (it < 2) ? 1 : 0);
        if (it < 2) k_update<<<NCAPS * SEQL, 256>>>();
    }
}

// round 5
// speedup vs baseline: 2.7035x; 1.1484x over previous
#include <cuda_runtime.h>
#include <cuda_bf16.h>
#include <math.h>
#include <stdint.h>

typedef unsigned long long ull;

#define NBATCH 1024
#define SEQL   200
#define DIM    256
#define NCAPS  8

// tcgen05 is arch-SPECIFIC: only legal on sm_103a/sm_100a compilation variants.
// The harness also runs a generic compute_103 PTX pass; give it a fallback.
#if !defined(__CUDA_ARCH__) || defined(__CUDA_ARCH_FEAT_SM103_ALL) || \
    defined(__CUDA_ARCH_FEAT_SM100_ALL) || defined(__CUDA_ARCH_FEAT_SM101_ALL)
#define TC_OK 1
#else
#define TC_OK 0
#endif

// ---------------- device scratch (no allocations allowed) ----------------
__device__ float g_mapped[(size_t)NBATCH * SEQL * DIM];   // 209.7 MB
__device__ float g_logits[NCAPS * SEQL];                  // 6.4 KB
__device__ float g_part[(size_t)NCAPS * SEQL * NBATCH];   // [k*L][b] transposed
__device__ __nv_bfloat16 g_WhT[DIM * DIM];                // W^T hi split, [n][k]
__device__ __nv_bfloat16 g_WlT[DIM * DIM];                // W^T lo split, [n][k]

// ---------------- f32x2 helpers ------------------------------------------
__device__ __forceinline__ ull ffma2(ull a, ull b, ull c) {
    ull d;
    asm("fma.rn.f32x2 %0, %1, %2, %3;" : "=l"(d) : "l"(a), "l"(b), "l"(c));
    return d;
}
__device__ __forceinline__ ull dup2(float x) {
    ull d;
    asm("mov.b64 %0, {%1, %1};" : "=l"(d) : "f"(x));
    return d;
}
__device__ __forceinline__ float2 unpack2(ull a) {
    float2 f;
    asm("mov.b64 {%0, %1}, %2;" : "=f"(f.x), "=f"(f.y) : "l"(a));
    return f;
}

// ---------------- tcgen05 / mbarrier PTX helpers -------------------------
__device__ __forceinline__ uint32_t smem_u32(const void* p) {
    uint32_t a;
    asm("{ .reg .u64 t; cvta.to.shared.u64 t, %1; cvt.u32.u64 %0, t; }"
        : "=r"(a) : "l"(p));
    return a;
}

#if TC_OK
__device__ __forceinline__ uint32_t elect1() {
    uint32_t p;
    asm volatile("{ .reg .pred p; elect.sync _|p, 0xFFFFFFFF; selp.b32 %0,1,0,p; }"
                 : "=r"(p));
    return p;
}
__device__ __forceinline__ void mma_f16_ss(uint32_t d, uint64_t a, uint64_t b,
                                           uint32_t id, uint32_t en) {
    asm volatile(
        "{\n\t.reg .pred p;\n\tsetp.ne.u32 p, %5, 0;\n\t"
        "tcgen05.mma.cta_group::1.kind::f16 [%0], %1, %2, %3, {%4,%4,%4,%4}, p;\n\t}"
        :: "r"(d), "l"(a), "l"(b), "r"(id), "r"(0u), "r"(en) : "memory");
}
__device__ __forceinline__ void mbar_wait(uint32_t a, uint32_t par) {
    asm volatile(
        "{\n\t.reg .pred P;\n"
        "W%=:\n\t"
        "mbarrier.try_wait.parity.acquire.cta.shared::cta.b64 P, [%0], %1, 0x989680;\n\t"
        "@P bra D%=;\n\t"
        "bra W%=;\n"
        "D%=:\n\t}" :: "r"(a), "r"(par) : "memory");
}
#define LDTM_X32(r, addr) \
    asm volatile( \
        "tcgen05.ld.sync.aligned.32x32b.x32.b32 " \
        "{%0,%1,%2,%3,%4,%5,%6,%7,%8,%9,%10,%11,%12,%13,%14,%15," \
        "%16,%17,%18,%19,%20,%21,%22,%23,%24,%25,%26,%27,%28,%29,%30,%31}, [%32];" \
        : "=r"((r)[0]),"=r"((r)[1]),"=r"((r)[2]),"=r"((r)[3]), \
          "=r"((r)[4]),"=r"((r)[5]),"=r"((r)[6]),"=r"((r)[7]), \
          "=r"((r)[8]),"=r"((r)[9]),"=r"((r)[10]),"=r"((r)[11]), \
          "=r"((r)[12]),"=r"((r)[13]),"=r"((r)[14]),"=r"((r)[15]), \
          "=r"((r)[16]),"=r"((r)[17]),"=r"((r)[18]),"=r"((r)[19]), \
          "=r"((r)[20]),"=r"((r)[21]),"=r"((r)[22]),"=r"((r)[23]), \
          "=r"((r)[24]),"=r"((r)[25]),"=r"((r)[26]),"=r"((r)[27]), \
          "=r"((r)[28]),"=r"((r)[29]),"=r"((r)[30]),"=r"((r)[31]) \
        : "r"(addr))
#endif  // TC_OK

// ---------------- init kernels -------------------------------------------
__global__ void k_init(const float* __restrict__ rlog) {
    int i = blockIdx.x * blockDim.x + threadIdx.x;
    if (i < NCAPS * SEQL) g_logits[i] = rlog[i];
}

// split + transpose W: g_W*T[n][k] = split(W[k][n])
__global__ void k_convW(const float* __restrict__ W) {
    int k = blockIdx.x;
    int n = threadIdx.x;
    float v = W[k * DIM + n];
    __nv_bfloat16 h = __float2bfloat16(v);
    float r = v - __bfloat162float(h);
    g_WhT[n * DIM + k] = h;
    g_WlT[n * DIM + k] = __float2bfloat16(r);
}

// ---------------- tensor-core GEMM: g_mapped = A @ W ----------------------
// bf16-split 3-product, M=128 per CTA, N=256, K chunks of 64, SW128 SMEM.
// A-chunk LDGs for chunk c+1 are issued before the mbar_wait on chunk c so
// DRAM latency hides behind the MMA train.
#define OFF_AH 1024
#define OFF_AL 17408
#define OFF_BH 33792
#define OFF_BL 66560
#define GSM_BYTES 99328

__global__ __launch_bounds__(256) void k_gemm_tc(const float* __restrict__ A,
                                                 const float* __restrict__ W) {
#if TC_OK
    extern __shared__ __align__(16) float sm[];
    char* sb = (char*)sm;
    uint32_t sbase = smem_u32(sm);
    int tid = threadIdx.x, wid = tid >> 5;
    size_t m0 = (size_t)blockIdx.x * 128;

    if (wid == 0) {
        asm volatile("tcgen05.alloc.cta_group::1.sync.aligned.shared::cta.b32 [%0], %1;"
                     :: "r"(sbase), "r"(256u) : "memory");
        asm volatile("tcgen05.relinquish_alloc_permit.cta_group::1.sync.aligned;");
    }
    __syncthreads();
    uint32_t tb;
    asm volatile("ld.shared.b32 %0, [%1];" : "=r"(tb) : "r"(sbase));

    if (tid == 0)
        asm volatile("mbarrier.init.shared.b64 [%0], %1;"
                     :: "r"(sbase + 8), "r"(1u) : "memory");
    __syncthreads();

    const uint64_t DB = (2ULL << 61) | (1ULL << 46) | (64ULL << 32) | (1ULL << 16);
    uint64_t dAh = DB | (((uint64_t)(sbase + OFF_AH) >> 4) & 0x3FFF);
    uint64_t dAl = DB | (((uint64_t)(sbase + OFF_AL) >> 4) & 0x3FFF);
    uint64_t dBh = DB | (((uint64_t)(sbase + OFF_BH) >> 4) & 0x3FFF);
    uint64_t dBl = DB | (((uint64_t)(sbase + OFF_BL) >> 4) & 0x3FFF);
    // idesc: F32 acc, BF16 a/b, N=256, M=128
    const uint32_t idesc = (1u << 4) | (1u << 7) | (1u << 10) |
                           ((DIM / 8) << 17) | ((128 / 16) << 24);

    const int la_r = tid >> 4, la_c4 = tid & 15;

    // prefetch chunk 0 of A
    float4 fA[8];
#pragma unroll
    for (int i = 0; i < 8; i++) {
        int idx = tid + i * 256;
        int r = idx >> 4, c4 = idx & 15;
        fA[i] = *(const float4*)(A + (m0 + r) * DIM + 0 + c4 * 4);
    }

    uint32_t first = 0;  // en = first != 0
    for (int c = 0; c < 4; c++) {
        int k0 = c * 64;
        // --- A chunk from regs: split bf16, swizzled STS ---
#pragma unroll
        for (int i = 0; i < 8; i++) {
            int idx = tid + i * 256;
            int r = idx >> 4, c4 = idx & 15;
            float4 f = fA[i];
            __nv_bfloat16 h0 = __float2bfloat16(f.x), h1 = __float2bfloat16(f.y),
                          h2 = __float2bfloat16(f.z), h3 = __float2bfloat16(f.w);
            float l0 = f.x - __bfloat162float(h0), l1 = f.y - __bfloat162float(h1),
                  l2 = f.z - __bfloat162float(h2), l3 = f.w - __bfloat162float(h3);
            uint32_t off = r * 128 + c4 * 8;
            uint32_t sw = off ^ ((off >> 3) & 0x70);
            uint2 uh, ulv;
            uh.x = ((uint32_t)__bfloat16_as_ushort(h1) << 16) | __bfloat16_as_ushort(h0);
            uh.y = ((uint32_t)__bfloat16_as_ushort(h3) << 16) | __bfloat16_as_ushort(h2);
            __nv_bfloat16 q0 = __float2bfloat16(l0), q1 = __float2bfloat16(l1),
                          q2 = __float2bfloat16(l2), q3 = __float2bfloat16(l3);
            ulv.x = ((uint32_t)__bfloat16_as_ushort(q1) << 16) | __bfloat16_as_ushort(q0);
            ulv.y = ((uint32_t)__bfloat16_as_ushort(q3) << 16) | __bfloat16_as_ushort(q2);
            *(uint2*)(sb + OFF_AH + sw) = uh;
            *(uint2*)(sb + OFF_AL + sw) = ulv;
        }
        // --- B chunk: 256 rows x 64 bf16 (both splits), L2-resident LDG ---
#pragma unroll
        for (int i = 0; i < 8; i++) {
            int idx = tid + i * 256;
            int r = idx >> 3, cc = idx & 7;
            uint32_t off = r * 128 + cc * 16;
            uint32_t sw = off ^ ((off >> 3) & 0x70);
            uint4 vh = *(const uint4*)((const char*)g_WhT + r * 512 + k0 * 2 + cc * 16);
            uint4 vl = *(const uint4*)((const char*)g_WlT + r * 512 + k0 * 2 + cc * 16);
            *(uint4*)(sb + OFF_BH + sw) = vh;
            *(uint4*)(sb + OFF_BL + sw) = vl;
        }
        __syncthreads();
        if (wid == 0) {
            asm volatile("fence.proxy.async.shared::cta;" ::: "memory");
            if (elect1()) {
#pragma unroll
                for (int s = 0; s < 4; s++) {
                    mma_f16_ss(tb, dAh + s * 2, dBh + s * 2, idesc, first);
                    first = 1;
                    mma_f16_ss(tb, dAh + s * 2, dBl + s * 2, idesc, 1);
                    mma_f16_ss(tb, dAl + s * 2, dBh + s * 2, idesc, 1);
                }
                asm volatile(
                    "tcgen05.commit.cta_group::1.mbarrier::arrive::one.shared::cluster.b64 [%0];"
                    :: "r"(sbase + 8) : "memory");
            }
        }
        // prefetch next A chunk while MMA runs
        if (c < 3) {
            int kn = k0 + 64;
#pragma unroll
            for (int i = 0; i < 8; i++) {
                int idx = tid + i * 256;
                int r = idx >> 4, c4 = idx & 15;
                fA[i] = *(const float4*)(A + (m0 + r) * DIM + kn + c4 * 4);
            }
        }
        mbar_wait(sbase + 8, (uint32_t)(c & 1));
    }
    (void)la_r; (void)la_c4;

    asm volatile("tcgen05.fence::after_thread_sync;" ::: "memory");
    if (tid < 128) {
        float* Crow = g_mapped + (m0 + tid) * DIM;
#pragma unroll
        for (int j = 0; j < 8; j++) {
            uint32_t r[32];
            LDTM_X32(r, tb + j * 32);
            asm volatile("tcgen05.wait::ld.sync.aligned;" ::: "memory");
#pragma unroll
            for (int q = 0; q < 8; q++) {
                float4 v = make_float4(__uint_as_float(r[q * 4 + 0]),
                                       __uint_as_float(r[q * 4 + 1]),
                                       __uint_as_float(r[q * 4 + 2]),
                                       __uint_as_float(r[q * 4 + 3]));
                *(float4*)(Crow + j * 32 + q * 4) = v;
            }
        }
    }
    __syncthreads();
    if (wid == 0) {
        asm volatile("tcgen05.dealloc.cta_group::1.sync.aligned.b32 %0, %1;"
                     :: "r"(tb), "r"(256u));
    }
#else
    // Generic-PTX fallback (never executed on GB300; sm_103a cubin is loaded).
    size_t m0 = (size_t)blockIdx.x * 128;
    int tid = threadIdx.x;
    for (int e = tid; e < 128 * 256; e += 256) {
        int r = e >> 8, n = e & 255;
        float acc = 0.f;
        for (int k = 0; k < DIM; k++)
            acc += A[(m0 + r) * DIM + k] * W[k * DIM + n];
        g_mapped[(m0 + r) * DIM + n] = acc;
    }
#endif
}

// ---------------- fused routing iteration: CTA per batch ------------------
// Streams mapped_b straight from global (no SMEM staging) -> 2 CTAs/SM.
__global__ __launch_bounds__(256, 2) void k_capsule(const int* __restrict__ seq_len,
                                                    float* __restrict__ out,
                                                    int do_delta) {
    __shared__ __align__(16) float sm_w[SEQL * NCAPS];     // 6.4 KB, l-major
    __shared__ __align__(16) float sm_caps[NCAPS * DIM];   // 8 KB
    __shared__ float sm_red[64];
    __shared__ float sm_sc[8];

    int b = blockIdx.x;
    int tid = threadIdx.x;
    int warp = tid >> 5, lane = tid & 31;
    int seq = seq_len[b];

    // ---- masked softmax over l for capsule k = warp ----
    {
        int k = warp;
        float vals[7];
        float mx = -INFINITY;
#pragma unroll
        for (int j = 0; j < 7; j++) {
            int l = lane + 32 * j;
            float v = (l < seq) ? g_logits[k * SEQL + l] : -INFINITY;
            vals[j] = v;
            mx = fmaxf(mx, v);
        }
#pragma unroll
        for (int off = 16; off; off >>= 1)
            mx = fmaxf(mx, __shfl_xor_sync(0xffffffffu, mx, off));
        float s = 0.f;
#pragma unroll
        for (int j = 0; j < 7; j++) {
            float e = expf(vals[j] - mx);
            vals[j] = e;
            s += e;
        }
#pragma unroll
        for (int off = 16; off; off >>= 1)
            s += __shfl_xor_sync(0xffffffffu, s, off);
        float inv = 1.f / s;
#pragma unroll
        for (int j = 0; j < 7; j++) {
            int l = lane + 32 * j;
            if (l < SEQL) sm_w[l * NCAPS + k] = vals[j] * inv;
        }
    }
    __syncthreads();

    const float* __restrict__ mb = g_mapped + (size_t)b * (SEQL * DIM);

    // ---- Z[k][o] = sum_l w[k][l]*m[l][o]; thread owns o, unroll-4 l ----
    int o = tid;
    ull z2[4] = {0ULL, 0ULL, 0ULL, 0ULL};
    int l = 0;
    for (; l + 4 <= seq; l += 4) {
        float m0 = mb[(size_t)(l + 0) * DIM + o];
        float m1 = mb[(size_t)(l + 1) * DIM + o];
        float m2 = mb[(size_t)(l + 2) * DIM + o];
        float m3 = mb[(size_t)(l + 3) * DIM + o];
        float mm[4] = {m0, m1, m2, m3};
#pragma unroll
        for (int j = 0; j < 4; j++) {
            ull md = dup2(mm[j]);
            ulonglong2 wa = *(const ulonglong2*)&sm_w[(l + j) * NCAPS];
            ulonglong2 wb = *(const ulonglong2*)&sm_w[(l + j) * NCAPS + 4];
            z2[0] = ffma2(md, wa.x, z2[0]);
            z2[1] = ffma2(md, wa.y, z2[1]);
            z2[2] = ffma2(md, wb.x, z2[2]);
            z2[3] = ffma2(md, wb.y, z2[3]);
        }
    }
    for (; l < seq; l++) {
        ull md = dup2(mb[(size_t)l * DIM + o]);
        ulonglong2 wa = *(const ulonglong2*)&sm_w[l * NCAPS];
        ulonglong2 wb = *(const ulonglong2*)&sm_w[l * NCAPS + 4];
        z2[0] = ffma2(md, wa.x, z2[0]);
        z2[1] = ffma2(md, wa.y, z2[1]);
        z2[2] = ffma2(md, wb.x, z2[2]);
        z2[3] = ffma2(md, wb.y, z2[3]);
    }
    float z[8];
    {
        float2 f;
        f = unpack2(z2[0]); z[0] = f.x; z[1] = f.y;
        f = unpack2(z2[1]); z[2] = f.x; z[3] = f.y;
        f = unpack2(z2[2]); z[4] = f.x; z[5] = f.y;
        f = unpack2(z2[3]); z[6] = f.x; z[7] = f.y;
    }

    // ---- squash ----
    {
        float zs[8];
#pragma unroll
        for (int k = 0; k < 8; k++) zs[k] = z[k] * z[k];
#pragma unroll
        for (int off = 16; off; off >>= 1)
#pragma unroll
            for (int k = 0; k < 8; k++)
                zs[k] += __shfl_xor_sync(0xffffffffu, zs[k], off);
        if (lane == 0) {
#pragma unroll
            for (int k = 0; k < 8; k++) sm_red[k * 8 + warp] = zs[k];
        }
    }
    __syncthreads();
    if (tid < 8) {
        float sq = 0.f;
#pragma unroll
        for (int w = 0; w < 8; w++) sq += sm_red[tid * 8 + w];
        sm_sc[tid] = sq / (1.f + sq) / sqrtf(sq + 1e-8f);
    }
    __syncthreads();

    // ---- capsules = scale * Z; out written only on final iteration ----
#pragma unroll
    for (int k = 0; k < 8; k++) {
        float c = sm_sc[k] * z[k];
        sm_caps[k * DIM + o] = c;
        if (!do_delta) out[((size_t)b * NCAPS + k) * DIM + o] = c;
    }

    // ---- delta[k][l] = sum_o caps[k][o]*m[l][o] (all l), transposed store ----
    if (do_delta) {
        __syncthreads();
        float4 c0[8], c1[8];
#pragma unroll
        for (int k = 0; k < 8; k++) {
            c0[k] = *(const float4*)&sm_caps[k * DIM + lane * 8];
            c1[k] = *(const float4*)&sm_caps[k * DIM + lane * 8 + 4];
        }
        for (int ld = warp; ld < SEQL; ld += 8) {
            float4 m0 = *(const float4*)&mb[(size_t)ld * DIM + lane * 8];
            float4 m1 = *(const float4*)&mb[(size_t)ld * DIM + lane * 8 + 4];
            float p[8];
#pragma unroll
            for (int k = 0; k < 8; k++) {
                p[k] = c0[k].x * m0.x + c0[k].y * m0.y + c0[k].z * m0.z + c0[k].w * m0.w
                     + c1[k].x * m1.x + c1[k].y * m1.y + c1[k].z * m1.z + c1[k].w * m1.w;
            }
#pragma unroll
            for (int off = 16; off; off >>= 1)
#pragma unroll
                for (int k = 0; k < 8; k++)
                    p[k] += __shfl_xor_sync(0xffffffffu, p[k], off);
            if (lane == 0) {
#pragma unroll
                for (int k = 0; k < 8; k++)
                    g_part[((size_t)k * SEQL + ld) * NBATCH + b] = p[k];
            }
        }
    }
}

// ---------------- deterministic batch-reduce of delta into logits --------
// g_part is [k*L][b]: each block reads a contiguous 4 KB row.
__global__ __launch_bounds__(256) void k_update() {
    __shared__ float red[256];
    int i = blockIdx.x;  // 0..1599
    const float* row = g_part + (size_t)i * NBATCH;
    float s = 0.f;
#pragma unroll
    for (int b = threadIdx.x; b < NBATCH; b += 256) s += row[b];
    red[threadIdx.x] = s;
    __syncthreads();
#pragma unroll
    for (int st = 128; st; st >>= 1) {
        if (threadIdx.x < st) red[threadIdx.x] += red[threadIdx.x + st];
        __syncthreads();
    }
    if (threadIdx.x == 0) g_logits[i] += red[0];
}

// ---------------- launch --------------------------------------------------
extern "C" void kernel_launch(void* const* d_in, const int* in_sizes, int n_in,
                              void* d_out, int out_size) {
    const float* emb  = (const float*)d_in[0];
    const int*   seq  = (const int*)d_in[1];
    const float* rlog = (const float*)d_in[2];
    const float* W    = (const float*)d_in[3];
    float* out = (float*)d_out;

    cudaFuncSetAttribute(k_gemm_tc, cudaFuncAttributeMaxDynamicSharedMemorySize,
                         GSM_BYTES);

    k_init<<<(NCAPS * SEQL + 255) / 256, 256>>>(rlog);
    k_convW<<<DIM, DIM>>>(W);
    k_gemm_tc<<<(NBATCH * SEQL) / 128, 256, GSM_BYTES>>>(emb, W);

    for (int it = 0; it < 3; it++) {
        k_capsule<<<NBATCH, 256>>>(seq, out, (it < 2) ? 1 : 0);
        if (it < 2) k_update<<<NCAPS * SEQL, 256>>>();
    }
}

// round 6
// speedup vs baseline: 2.9452x; 1.0894x over previous
#include <cuda_runtime.h>
#include <cuda_bf16.h>
#include <math.h>
#include <stdint.h>

typedef unsigned long long ull;

#define NBATCH 1024
#define SEQL   200
#define DIM    256
#define NCAPS  8

// tcgen05 is arch-SPECIFIC: only legal on sm_103a/sm_100a compilation variants.
// The harness also runs a generic compute_103 PTX pass; give it a fallback.
#if !defined(__CUDA_ARCH__) || defined(__CUDA_ARCH_FEAT_SM103_ALL) || \
    defined(__CUDA_ARCH_FEAT_SM100_ALL) || defined(__CUDA_ARCH_FEAT_SM101_ALL)
#define TC_OK 1
#else
#define TC_OK 0
#endif

// ---------------- device scratch (no allocations allowed) ----------------
__device__ float g_mapped[(size_t)NBATCH * SEQL * DIM];   // 209.7 MB
__device__ float g_logits[NCAPS * SEQL];                  // 6.4 KB
__device__ float g_part[(size_t)NCAPS * SEQL * NBATCH];   // [k*L][b]
__device__ __nv_bfloat16 g_WhT[DIM * DIM];                // W^T hi split, [n][k]
__device__ __nv_bfloat16 g_WlT[DIM * DIM];                // W^T lo split, [n][k]

// ---------------- f32x2 helpers ------------------------------------------
__device__ __forceinline__ ull ffma2(ull a, ull b, ull c) {
    ull d;
    asm("fma.rn.f32x2 %0, %1, %2, %3;" : "=l"(d) : "l"(a), "l"(b), "l"(c));
    return d;
}
__device__ __forceinline__ ull dup2(float x) {
    ull d;
    asm("mov.b64 %0, {%1, %1};" : "=l"(d) : "f"(x));
    return d;
}
__device__ __forceinline__ float2 unpack2(ull a) {
    float2 f;
    asm("mov.b64 {%0, %1}, %2;" : "=f"(f.x), "=f"(f.y) : "l"(a));
    return f;
}

// ---------------- tcgen05 / mbarrier PTX helpers -------------------------
__device__ __forceinline__ uint32_t smem_u32(const void* p) {
    uint32_t a;
    asm("{ .reg .u64 t; cvta.to.shared.u64 t, %1; cvt.u32.u64 %0, t; }"
        : "=r"(a) : "l"(p));
    return a;
}

#if TC_OK
__device__ __forceinline__ uint32_t elect1() {
    uint32_t p;
    asm volatile("{ .reg .pred p; elect.sync _|p, 0xFFFFFFFF; selp.b32 %0,1,0,p; }"
                 : "=r"(p));
    return p;
}
__device__ __forceinline__ void mma_f16_ss(uint32_t d, uint64_t a, uint64_t b,
                                           uint32_t id, uint32_t en) {
    asm volatile(
        "{\n\t.reg .pred p;\n\tsetp.ne.u32 p, %5, 0;\n\t"
        "tcgen05.mma.cta_group::1.kind::f16 [%0], %1, %2, %3, {%4,%4,%4,%4}, p;\n\t}"
        :: "r"(d), "l"(a), "l"(b), "r"(id), "r"(0u), "r"(en) : "memory");
}
__device__ __forceinline__ void mbar_wait(uint32_t a, uint32_t par) {
    asm volatile(
        "{\n\t.reg .pred P;\n"
        "W%=:\n\t"
        "mbarrier.try_wait.parity.acquire.cta.shared::cta.b64 P, [%0], %1, 0x989680;\n\t"
        "@P bra D%=;\n\t"
        "bra W%=;\n"
        "D%=:\n\t}" :: "r"(a), "r"(par) : "memory");
}
#define LDTM_X32(r, addr) \
    asm volatile( \
        "tcgen05.ld.sync.aligned.32x32b.x32.b32 " \
        "{%0,%1,%2,%3,%4,%5,%6,%7,%8,%9,%10,%11,%12,%13,%14,%15," \
        "%16,%17,%18,%19,%20,%21,%22,%23,%24,%25,%26,%27,%28,%29,%30,%31}, [%32];" \
        : "=r"((r)[0]),"=r"((r)[1]),"=r"((r)[2]),"=r"((r)[3]), \
          "=r"((r)[4]),"=r"((r)[5]),"=r"((r)[6]),"=r"((r)[7]), \
          "=r"((r)[8]),"=r"((r)[9]),"=r"((r)[10]),"=r"((r)[11]), \
          "=r"((r)[12]),"=r"((r)[13]),"=r"((r)[14]),"=r"((r)[15]), \
          "=r"((r)[16]),"=r"((r)[17]),"=r"((r)[18]),"=r"((r)[19]), \
          "=r"((r)[20]),"=r"((r)[21]),"=r"((r)[22]),"=r"((r)[23]), \
          "=r"((r)[24]),"=r"((r)[25]),"=r"((r)[26]),"=r"((r)[27]), \
          "=r"((r)[28]),"=r"((r)[29]),"=r"((r)[30]),"=r"((r)[31]) \
        : "r"(addr))
#endif  // TC_OK

// ---------------- init kernels -------------------------------------------
__global__ void k_init(const float* __restrict__ rlog) {
    int i = blockIdx.x * blockDim.x + threadIdx.x;
    if (i < NCAPS * SEQL) g_logits[i] = rlog[i];
}

// split + transpose W: g_W*T[n][k] = split(W[k][n])
__global__ void k_convW(const float* __restrict__ W) {
    int k = blockIdx.x;
    int n = threadIdx.x;
    float v = W[k * DIM + n];
    __nv_bfloat16 h = __float2bfloat16(v);
    float r = v - __bfloat162float(h);
    g_WhT[n * DIM + k] = h;
    g_WlT[n * DIM + k] = __float2bfloat16(r);
}

// ---------------- tensor-core GEMM: g_mapped = A @ W ----------------------
#define OFF_AH 1024
#define OFF_AL 17408
#define OFF_BH 33792
#define OFF_BL 66560
#define GSM_BYTES 99328

__global__ __launch_bounds__(256) void k_gemm_tc(const float* __restrict__ A,
                                                 const float* __restrict__ W) {
#if TC_OK
    extern __shared__ __align__(16) float sm[];
    char* sb = (char*)sm;
    uint32_t sbase = smem_u32(sm);
    int tid = threadIdx.x, wid = tid >> 5;
    size_t m0 = (size_t)blockIdx.x * 128;

    if (wid == 0) {
        asm volatile("tcgen05.alloc.cta_group::1.sync.aligned.shared::cta.b32 [%0], %1;"
                     :: "r"(sbase), "r"(256u) : "memory");
        asm volatile("tcgen05.relinquish_alloc_permit.cta_group::1.sync.aligned;");
    }
    __syncthreads();
    uint32_t tb;
    asm volatile("ld.shared.b32 %0, [%1];" : "=r"(tb) : "r"(sbase));

    if (tid == 0)
        asm volatile("mbarrier.init.shared.b64 [%0], %1;"
                     :: "r"(sbase + 8), "r"(1u) : "memory");
    __syncthreads();

    const uint64_t DB = (2ULL << 61) | (1ULL << 46) | (64ULL << 32) | (1ULL << 16);
    uint64_t dAh = DB | (((uint64_t)(sbase + OFF_AH) >> 4) & 0x3FFF);
    uint64_t dAl = DB | (((uint64_t)(sbase + OFF_AL) >> 4) & 0x3FFF);
    uint64_t dBh = DB | (((uint64_t)(sbase + OFF_BH) >> 4) & 0x3FFF);
    uint64_t dBl = DB | (((uint64_t)(sbase + OFF_BL) >> 4) & 0x3FFF);
    const uint32_t idesc = (1u << 4) | (1u << 7) | (1u << 10) |
                           ((DIM / 8) << 17) | ((128 / 16) << 24);

    // prefetch chunk 0 of A
    float4 fA[8];
#pragma unroll
    for (int i = 0; i < 8; i++) {
        int idx = tid + i * 256;
        int r = idx >> 4, c4 = idx & 15;
        fA[i] = *(const float4*)(A + (m0 + r) * DIM + 0 + c4 * 4);
    }

    uint32_t first = 0;
    for (int c = 0; c < 4; c++) {
        int k0 = c * 64;
#pragma unroll
        for (int i = 0; i < 8; i++) {
            int idx = tid + i * 256;
            int r = idx >> 4, c4 = idx & 15;
            float4 f = fA[i];
            __nv_bfloat16 h0 = __float2bfloat16(f.x), h1 = __float2bfloat16(f.y),
                          h2 = __float2bfloat16(f.z), h3 = __float2bfloat16(f.w);
            float l0 = f.x - __bfloat162float(h0), l1 = f.y - __bfloat162float(h1),
                  l2 = f.z - __bfloat162float(h2), l3 = f.w - __bfloat162float(h3);
            uint32_t off = r * 128 + c4 * 8;
            uint32_t sw = off ^ ((off >> 3) & 0x70);
            uint2 uh, ulv;
            uh.x = ((uint32_t)__bfloat16_as_ushort(h1) << 16) | __bfloat16_as_ushort(h0);
            uh.y = ((uint32_t)__bfloat16_as_ushort(h3) << 16) | __bfloat16_as_ushort(h2);
            __nv_bfloat16 q0 = __float2bfloat16(l0), q1 = __float2bfloat16(l1),
                          q2 = __float2bfloat16(l2), q3 = __float2bfloat16(l3);
            ulv.x = ((uint32_t)__bfloat16_as_ushort(q1) << 16) | __bfloat16_as_ushort(q0);
            ulv.y = ((uint32_t)__bfloat16_as_ushort(q3) << 16) | __bfloat16_as_ushort(q2);
            *(uint2*)(sb + OFF_AH + sw) = uh;
            *(uint2*)(sb + OFF_AL + sw) = ulv;
        }
#pragma unroll
        for (int i = 0; i < 8; i++) {
            int idx = tid + i * 256;
            int r = idx >> 3, cc = idx & 7;
            uint32_t off = r * 128 + cc * 16;
            uint32_t sw = off ^ ((off >> 3) & 0x70);
            uint4 vh = *(const uint4*)((const char*)g_WhT + r * 512 + k0 * 2 + cc * 16);
            uint4 vl = *(const uint4*)((const char*)g_WlT + r * 512 + k0 * 2 + cc * 16);
            *(uint4*)(sb + OFF_BH + sw) = vh;
            *(uint4*)(sb + OFF_BL + sw) = vl;
        }
        __syncthreads();
        if (wid == 0) {
            asm volatile("fence.proxy.async.shared::cta;" ::: "memory");
            if (elect1()) {
#pragma unroll
                for (int s = 0; s < 4; s++) {
                    mma_f16_ss(tb, dAh + s * 2, dBh + s * 2, idesc, first);
                    first = 1;
                    mma_f16_ss(tb, dAh + s * 2, dBl + s * 2, idesc, 1);
                    mma_f16_ss(tb, dAl + s * 2, dBh + s * 2, idesc, 1);
                }
                asm volatile(
                    "tcgen05.commit.cta_group::1.mbarrier::arrive::one.shared::cluster.b64 [%0];"
                    :: "r"(sbase + 8) : "memory");
            }
        }
        if (c < 3) {
            int kn = k0 + 64;
#pragma unroll
            for (int i = 0; i < 8; i++) {
                int idx = tid + i * 256;
                int r = idx >> 4, c4 = idx & 15;
                fA[i] = *(const float4*)(A + (m0 + r) * DIM + kn + c4 * 4);
            }
        }
        mbar_wait(sbase + 8, (uint32_t)(c & 1));
    }

    asm volatile("tcgen05.fence::after_thread_sync;" ::: "memory");
    if (tid < 128) {
        float* Crow = g_mapped + (m0 + tid) * DIM;
#pragma unroll
        for (int j = 0; j < 8; j++) {
            uint32_t r[32];
            LDTM_X32(r, tb + j * 32);
            asm volatile("tcgen05.wait::ld.sync.aligned;" ::: "memory");
#pragma unroll
            for (int q = 0; q < 8; q++) {
                float4 v = make_float4(__uint_as_float(r[q * 4 + 0]),
                                       __uint_as_float(r[q * 4 + 1]),
                                       __uint_as_float(r[q * 4 + 2]),
                                       __uint_as_float(r[q * 4 + 3]));
                *(float4*)(Crow + j * 32 + q * 4) = v;
            }
        }
    }
    __syncthreads();
    if (wid == 0) {
        asm volatile("tcgen05.dealloc.cta_group::1.sync.aligned.b32 %0, %1;"
                     :: "r"(tb), "r"(256u));
    }
#else
    size_t m0 = (size_t)blockIdx.x * 128;
    int tid = threadIdx.x;
    for (int e = tid; e < 128 * 256; e += 256) {
        int r = e >> 8, n = e & 255;
        float acc = 0.f;
        for (int k = 0; k < DIM; k++)
            acc += A[(m0 + r) * DIM + k] * W[k * DIM + n];
        g_mapped[(m0 + r) * DIM + n] = acc;
    }
#endif
}

// ---------------- k_caps: softmax + Z + squash, CTA per batch -------------
// Low-register, 4 CTAs/SM; Z streams mapped rows with unroll-8 MLP.
// Capsules written to `out` every iteration (delta kernel reads them there).
__global__ __launch_bounds__(256, 4) void k_caps(const int* __restrict__ seq_len,
                                                 float* __restrict__ out) {
    __shared__ __align__(16) float sm_w[SEQL * NCAPS];  // 6.4 KB, l-major
    __shared__ float sm_red[64];
    __shared__ float sm_sc[8];

    int b = blockIdx.x;
    int tid = threadIdx.x;
    int warp = tid >> 5, lane = tid & 31;
    int seq = seq_len[b];

    // ---- masked softmax over l for capsule k = warp ----
    {
        int k = warp;
        float vals[7];
        float mx = -INFINITY;
#pragma unroll
        for (int j = 0; j < 7; j++) {
            int l = lane + 32 * j;
            float v = (l < seq) ? g_logits[k * SEQL + l] : -INFINITY;
            vals[j] = v;
            mx = fmaxf(mx, v);
        }
#pragma unroll
        for (int off = 16; off; off >>= 1)
            mx = fmaxf(mx, __shfl_xor_sync(0xffffffffu, mx, off));
        float s = 0.f;
#pragma unroll
        for (int j = 0; j < 7; j++) {
            float e = expf(vals[j] - mx);
            vals[j] = e;
            s += e;
        }
#pragma unroll
        for (int off = 16; off; off >>= 1)
            s += __shfl_xor_sync(0xffffffffu, s, off);
        float inv = 1.f / s;
#pragma unroll
        for (int j = 0; j < 7; j++) {
            int l = lane + 32 * j;
            if (l < SEQL) sm_w[l * NCAPS + k] = vals[j] * inv;
        }
    }
    __syncthreads();

    const float* __restrict__ mb = g_mapped + (size_t)b * (SEQL * DIM);

    // ---- Z[k][o] = sum_l w[k][l]*m[l][o]; thread owns o, unroll-8 ----
    int o = tid;
    ull z2[4] = {0ULL, 0ULL, 0ULL, 0ULL};
    int l = 0;
    for (; l + 8 <= seq; l += 8) {
        float mm[8];
#pragma unroll
        for (int j = 0; j < 8; j++)
            mm[j] = mb[(size_t)(l + j) * DIM + o];
#pragma unroll
        for (int j = 0; j < 8; j++) {
            ull md = dup2(mm[j]);
            ulonglong2 wa = *(const ulonglong2*)&sm_w[(l + j) * NCAPS];
            ulonglong2 wb = *(const ulonglong2*)&sm_w[(l + j) * NCAPS + 4];
            z2[0] = ffma2(md, wa.x, z2[0]);
            z2[1] = ffma2(md, wa.y, z2[1]);
            z2[2] = ffma2(md, wb.x, z2[2]);
            z2[3] = ffma2(md, wb.y, z2[3]);
        }
    }
    for (; l < seq; l++) {
        ull md = dup2(mb[(size_t)l * DIM + o]);
        ulonglong2 wa = *(const ulonglong2*)&sm_w[l * NCAPS];
        ulonglong2 wb = *(const ulonglong2*)&sm_w[l * NCAPS + 4];
        z2[0] = ffma2(md, wa.x, z2[0]);
        z2[1] = ffma2(md, wa.y, z2[1]);
        z2[2] = ffma2(md, wb.x, z2[2]);
        z2[3] = ffma2(md, wb.y, z2[3]);
    }
    float z[8];
    {
        float2 f;
        f = unpack2(z2[0]); z[0] = f.x; z[1] = f.y;
        f = unpack2(z2[1]); z[2] = f.x; z[3] = f.y;
        f = unpack2(z2[2]); z[4] = f.x; z[5] = f.y;
        f = unpack2(z2[3]); z[6] = f.x; z[7] = f.y;
    }

    // ---- squash ----
    {
        float zs[8];
#pragma unroll
        for (int k = 0; k < 8; k++) zs[k] = z[k] * z[k];
#pragma unroll
        for (int off = 16; off; off >>= 1)
#pragma unroll
            for (int k = 0; k < 8; k++)
                zs[k] += __shfl_xor_sync(0xffffffffu, zs[k], off);
        if (lane == 0) {
#pragma unroll
            for (int k = 0; k < 8; k++) sm_red[k * 8 + warp] = zs[k];
        }
    }
    __syncthreads();
    if (tid < 8) {
        float sq = 0.f;
#pragma unroll
        for (int w = 0; w < 8; w++) sq += sm_red[tid * 8 + w];
        sm_sc[tid] = sq / (1.f + sq) / sqrtf(sq + 1e-8f);
    }
    __syncthreads();

#pragma unroll
    for (int k = 0; k < 8; k++)
        out[((size_t)b * NCAPS + k) * DIM + o] = sm_sc[k] * z[k];
}

// ---------------- k_delta: delta[k][l] per batch (partial, transposed) ----
// Warp w owns capsules kbase=(w>>2)*4 .. +3 and l-stripe (w&3)::4.
// 6-shfl multi-value reduction (V=4) instead of 40.
__global__ __launch_bounds__(256, 4) void k_delta(const float* __restrict__ caps) {
    int b = blockIdx.x;
    int tid = threadIdx.x;
    int warp = tid >> 5, lane = tid & 31;
    int kbase = (warp >> 2) * 4;
    int lphase = warp & 3;

    const float* __restrict__ mb = g_mapped + (size_t)b * (SEQL * DIM);
    const float* __restrict__ cb = caps + (size_t)b * (NCAPS * DIM);

    // caps for 4 owned capsules: 8 floats each at o = lane*8..+8
    float4 c0[4], c1[4];
#pragma unroll
    for (int k = 0; k < 4; k++) {
        c0[k] = *(const float4*)&cb[(kbase + k) * DIM + lane * 8];
        c1[k] = *(const float4*)&cb[(kbase + k) * DIM + lane * 8 + 4];
    }

    bool writer = (lane & 7) == 0;
    int kw = kbase + ((lane >> 4) & 1) * 2 + ((lane >> 3) & 1);

    for (int l = lphase; l < SEQL; l += 4) {
        float4 m0 = *(const float4*)&mb[(size_t)l * DIM + lane * 8];
        float4 m1 = *(const float4*)&mb[(size_t)l * DIM + lane * 8 + 4];
        float p[4];
#pragma unroll
        for (int k = 0; k < 4; k++) {
            p[k] = c0[k].x * m0.x + c0[k].y * m0.y + c0[k].z * m0.z + c0[k].w * m0.w
                 + c1[k].x * m1.x + c1[k].y * m1.y + c1[k].z * m1.z + c1[k].w * m1.w;
        }
        // multi-value reduce: stage off=16 (keep pair by bit4)
        bool hi4 = (lane & 16) != 0;
        float t0 = hi4 ? p[0] : p[2];
        float t1 = hi4 ? p[1] : p[3];
        t0 = __shfl_xor_sync(0xffffffffu, t0, 16);
        t1 = __shfl_xor_sync(0xffffffffu, t1, 16);
        float q0 = (hi4 ? p[2] : p[0]) + t0;
        float q1 = (hi4 ? p[3] : p[1]) + t1;
        // stage off=8 (keep one by bit3)
        bool hi3 = (lane & 8) != 0;
        float t = hi3 ? q0 : q1;
        t = __shfl_xor_sync(0xffffffffu, t, 8);
        float r = (hi3 ? q1 : q0) + t;
        // stages 4,2,1
        r += __shfl_xor_sync(0xffffffffu, r, 4);
        r += __shfl_xor_sync(0xffffffffu, r, 2);
        r += __shfl_xor_sync(0xffffffffu, r, 1);
        if (writer)
            g_part[((size_t)kw * SEQL + l) * NBATCH + b] = r;
    }
}

// ---------------- deterministic batch-reduce of delta into logits --------
// One block per (k,l); each thread one float4 from the contiguous 4 KB row.
__global__ __launch_bounds__(256) void k_update() {
    __shared__ float red[256];
    int i = blockIdx.x;  // 0..1599
    const float4* row = (const float4*)(g_part + (size_t)i * NBATCH);
    float4 v = row[threadIdx.x];
    red[threadIdx.x] = v.x + v.y + v.z + v.w;
    __syncthreads();
#pragma unroll
    for (int st = 128; st; st >>= 1) {
        if (threadIdx.x < st) red[threadIdx.x] += red[threadIdx.x + st];
        __syncthreads();
    }
    if (threadIdx.x == 0) g_logits[i] += red[0];
}

// ---------------- launch --------------------------------------------------
extern "C" void kernel_launch(void* const* d_in, const int* in_sizes, int n_in,
                              void* d_out, int out_size) {
    const float* emb  = (const float*)d_in[0];
    const int*   seq  = (const int*)d_in[1];
    const float* rlog = (const float*)d_in[2];
    const float* W    = (const float*)d_in[3];
    float* out = (float*)d_out;

    cudaFuncSetAttribute(k_gemm_tc, cudaFuncAttributeMaxDynamicSharedMemorySize,
                         GSM_BYTES);

    k_init<<<(NCAPS * SEQL + 255) / 256, 256>>>(rlog);
    k_convW<<<DIM, DIM>>>(W);
    k_gemm_tc<<<(NBATCH * SEQL) / 128, 256, GSM_BYTES>>>(emb, W);

    for (int it = 0; it < 3; it++) {
        k_caps<<<NBATCH, 256>>>(seq, out);
        if (it < 2) {
            k_delta<<<NBATCH, 256>>>(out);
            k_update<<<NCAPS * SEQL, 256>>>();
        }
    }
}

// round 7
// speedup vs baseline: 3.0360x; 1.0308x over previous
#include <cuda_runtime.h>
#include <cuda_bf16.h>
#include <math.h>
#include <stdint.h>

typedef unsigned long long ull;

#define NBATCH 1024
#define SEQL   200
#define DIM    256
#define NCAPS  8

// tcgen05 is arch-SPECIFIC: only legal on sm_103a/sm_100a compilation variants.
// The harness also runs a generic compute_103 PTX pass; give it a fallback.
#if !defined(__CUDA_ARCH__) || defined(__CUDA_ARCH_FEAT_SM103_ALL) || \
    defined(__CUDA_ARCH_FEAT_SM100_ALL) || defined(__CUDA_ARCH_FEAT_SM101_ALL)
#define TC_OK 1
#else
#define TC_OK 0
#endif

// ---------------- device scratch (no allocations allowed) ----------------
__device__ float g_mapped[(size_t)NBATCH * SEQL * DIM];   // 209.7 MB
__device__ float g_logits[NCAPS * SEQL];                  // 6.4 KB
__device__ float g_part[(size_t)NCAPS * SEQL * NBATCH];   // [k*L][b]
__device__ __nv_bfloat16 g_WhT[DIM * DIM];                // W^T hi split, [n][k]
__device__ __nv_bfloat16 g_WlT[DIM * DIM];                // W^T lo split, [n][k]

// ---------------- f32x2 helpers ------------------------------------------
__device__ __forceinline__ ull ffma2(ull a, ull b, ull c) {
    ull d;
    asm("fma.rn.f32x2 %0, %1, %2, %3;" : "=l"(d) : "l"(a), "l"(b), "l"(c));
    return d;
}
__device__ __forceinline__ ull dup2(float x) {
    ull d;
    asm("mov.b64 %0, {%1, %1};" : "=l"(d) : "f"(x));
    return d;
}
__device__ __forceinline__ float2 unpack2(ull a) {
    float2 f;
    asm("mov.b64 {%0, %1}, %2;" : "=f"(f.x), "=f"(f.y) : "l"(a));
    return f;
}

// ---------------- tcgen05 / mbarrier PTX helpers -------------------------
__device__ __forceinline__ uint32_t smem_u32(const void* p) {
    uint32_t a;
    asm("{ .reg .u64 t; cvta.to.shared.u64 t, %1; cvt.u32.u64 %0, t; }"
        : "=r"(a) : "l"(p));
    return a;
}

#if TC_OK
__device__ __forceinline__ uint32_t elect1() {
    uint32_t p;
    asm volatile("{ .reg .pred p; elect.sync _|p, 0xFFFFFFFF; selp.b32 %0,1,0,p; }"
                 : "=r"(p));
    return p;
}
__device__ __forceinline__ void mma_f16_ss(uint32_t d, uint64_t a, uint64_t b,
                                           uint32_t id, uint32_t en) {
    asm volatile(
        "{\n\t.reg .pred p;\n\tsetp.ne.u32 p, %5, 0;\n\t"
        "tcgen05.mma.cta_group::1.kind::f16 [%0], %1, %2, %3, {%4,%4,%4,%4}, p;\n\t}"
        :: "r"(d), "l"(a), "l"(b), "r"(id), "r"(0u), "r"(en) : "memory");
}
__device__ __forceinline__ void mbar_wait(uint32_t a, uint32_t par) {
    asm volatile(
        "{\n\t.reg .pred P;\n"
        "W%=:\n\t"
        "mbarrier.try_wait.parity.acquire.cta.shared::cta.b64 P, [%0], %1, 0x989680;\n\t"
        "@P bra D%=;\n\t"
        "bra W%=;\n"
        "D%=:\n\t}" :: "r"(a), "r"(par) : "memory");
}
#define LDTM_X32(r, addr) \
    asm volatile( \
        "tcgen05.ld.sync.aligned.32x32b.x32.b32 " \
        "{%0,%1,%2,%3,%4,%5,%6,%7,%8,%9,%10,%11,%12,%13,%14,%15," \
        "%16,%17,%18,%19,%20,%21,%22,%23,%24,%25,%26,%27,%28,%29,%30,%31}, [%32];" \
        : "=r"((r)[0]),"=r"((r)[1]),"=r"((r)[2]),"=r"((r)[3]), \
          "=r"((r)[4]),"=r"((r)[5]),"=r"((r)[6]),"=r"((r)[7]), \
          "=r"((r)[8]),"=r"((r)[9]),"=r"((r)[10]),"=r"((r)[11]), \
          "=r"((r)[12]),"=r"((r)[13]),"=r"((r)[14]),"=r"((r)[15]), \
          "=r"((r)[16]),"=r"((r)[17]),"=r"((r)[18]),"=r"((r)[19]), \
          "=r"((r)[20]),"=r"((r)[21]),"=r"((r)[22]),"=r"((r)[23]), \
          "=r"((r)[24]),"=r"((r)[25]),"=r"((r)[26]),"=r"((r)[27]), \
          "=r"((r)[28]),"=r"((r)[29]),"=r"((r)[30]),"=r"((r)[31]) \
        : "r"(addr))
#endif  // TC_OK

// ---------------- init kernels -------------------------------------------
__global__ void k_init(const float* __restrict__ rlog) {
    int i = blockIdx.x * blockDim.x + threadIdx.x;
    if (i < NCAPS * SEQL) g_logits[i] = rlog[i];
}

// split + transpose W: g_W*T[n][k] = split(W[k][n])
__global__ void k_convW(const float* __restrict__ W) {
    int k = blockIdx.x;
    int n = threadIdx.x;
    float v = W[k * DIM + n];
    __nv_bfloat16 h = __float2bfloat16(v);
    float r = v - __bfloat162float(h);
    g_WhT[n * DIM + k] = h;
    g_WlT[n * DIM + k] = __float2bfloat16(r);
}

// ---------------- tensor-core GEMM: g_mapped = A @ W ----------------------
// 2 CTAs/SM co-resident (99 KB SMEM, 256 TMEM cols each) so one CTA's MMA
// train overlaps the other's loads/epilogue.
#define OFF_AH 1024
#define OFF_AL 17408
#define OFF_BH 33792
#define OFF_BL 66560
#define GSM_BYTES 99328

__global__ __launch_bounds__(256, 2) void k_gemm_tc(const float* __restrict__ A,
                                                    const float* __restrict__ W) {
#if TC_OK
    extern __shared__ __align__(16) float sm[];
    char* sb = (char*)sm;
    uint32_t sbase = smem_u32(sm);
    int tid = threadIdx.x, wid = tid >> 5;
    size_t m0 = (size_t)blockIdx.x * 128;

    if (wid == 0) {
        asm volatile("tcgen05.alloc.cta_group::1.sync.aligned.shared::cta.b32 [%0], %1;"
                     :: "r"(sbase), "r"(256u) : "memory");
        asm volatile("tcgen05.relinquish_alloc_permit.cta_group::1.sync.aligned;");
    }
    __syncthreads();
    uint32_t tb;
    asm volatile("ld.shared.b32 %0, [%1];" : "=r"(tb) : "r"(sbase));

    if (tid == 0)
        asm volatile("mbarrier.init.shared.b64 [%0], %1;"
                     :: "r"(sbase + 8), "r"(1u) : "memory");
    __syncthreads();

    const uint64_t DB = (2ULL << 61) | (1ULL << 46) | (64ULL << 32) | (1ULL << 16);
    uint64_t dAh = DB | (((uint64_t)(sbase + OFF_AH) >> 4) & 0x3FFF);
    uint64_t dAl = DB | (((uint64_t)(sbase + OFF_AL) >> 4) & 0x3FFF);
    uint64_t dBh = DB | (((uint64_t)(sbase + OFF_BH) >> 4) & 0x3FFF);
    uint64_t dBl = DB | (((uint64_t)(sbase + OFF_BL) >> 4) & 0x3FFF);
    const uint32_t idesc = (1u << 4) | (1u << 7) | (1u << 10) |
                           ((DIM / 8) << 17) | ((128 / 16) << 24);

    // prefetch chunk 0 of A
    float4 fA[8];
#pragma unroll
    for (int i = 0; i < 8; i++) {
        int idx = tid + i * 256;
        int r = idx >> 4, c4 = idx & 15;
        fA[i] = *(const float4*)(A + (m0 + r) * DIM + 0 + c4 * 4);
    }

    uint32_t first = 0;
    for (int c = 0; c < 4; c++) {
        int k0 = c * 64;
#pragma unroll
        for (int i = 0; i < 8; i++) {
            int idx = tid + i * 256;
            int r = idx >> 4, c4 = idx & 15;
            float4 f = fA[i];
            __nv_bfloat16 h0 = __float2bfloat16(f.x), h1 = __float2bfloat16(f.y),
                          h2 = __float2bfloat16(f.z), h3 = __float2bfloat16(f.w);
            float l0 = f.x - __bfloat162float(h0), l1 = f.y - __bfloat162float(h1),
                  l2 = f.z - __bfloat162float(h2), l3 = f.w - __bfloat162float(h3);
            uint32_t off = r * 128 + c4 * 8;
            uint32_t sw = off ^ ((off >> 3) & 0x70);
            uint2 uh, ulv;
            uh.x = ((uint32_t)__bfloat16_as_ushort(h1) << 16) | __bfloat16_as_ushort(h0);
            uh.y = ((uint32_t)__bfloat16_as_ushort(h3) << 16) | __bfloat16_as_ushort(h2);
            __nv_bfloat16 q0 = __float2bfloat16(l0), q1 = __float2bfloat16(l1),
                          q2 = __float2bfloat16(l2), q3 = __float2bfloat16(l3);
            ulv.x = ((uint32_t)__bfloat16_as_ushort(q1) << 16) | __bfloat16_as_ushort(q0);
            ulv.y = ((uint32_t)__bfloat16_as_ushort(q3) << 16) | __bfloat16_as_ushort(q2);
            *(uint2*)(sb + OFF_AH + sw) = uh;
            *(uint2*)(sb + OFF_AL + sw) = ulv;
        }
#pragma unroll
        for (int i = 0; i < 8; i++) {
            int idx = tid + i * 256;
            int r = idx >> 3, cc = idx & 7;
            uint32_t off = r * 128 + cc * 16;
            uint32_t sw = off ^ ((off >> 3) & 0x70);
            uint4 vh = *(const uint4*)((const char*)g_WhT + r * 512 + k0 * 2 + cc * 16);
            uint4 vl = *(const uint4*)((const char*)g_WlT + r * 512 + k0 * 2 + cc * 16);
            *(uint4*)(sb + OFF_BH + sw) = vh;
            *(uint4*)(sb + OFF_BL + sw) = vl;
        }
        __syncthreads();
        if (wid == 0) {
            asm volatile("fence.proxy.async.shared::cta;" ::: "memory");
            if (elect1()) {
#pragma unroll
                for (int s = 0; s < 4; s++) {
                    mma_f16_ss(tb, dAh + s * 2, dBh + s * 2, idesc, first);
                    first = 1;
                    mma_f16_ss(tb, dAh + s * 2, dBl + s * 2, idesc, 1);
                    mma_f16_ss(tb, dAl + s * 2, dBh + s * 2, idesc, 1);
                }
                asm volatile(
                    "tcgen05.commit.cta_group::1.mbarrier::arrive::one.shared::cluster.b64 [%0];"
                    :: "r"(sbase + 8) : "memory");
            }
        }
        if (c < 3) {
            int kn = k0 + 64;
#pragma unroll
            for (int i = 0; i < 8; i++) {
                int idx = tid + i * 256;
                int r = idx >> 4, c4 = idx & 15;
                fA[i] = *(const float4*)(A + (m0 + r) * DIM + kn + c4 * 4);
            }
        }
        mbar_wait(sbase + 8, (uint32_t)(c & 1));
    }

    asm volatile("tcgen05.fence::after_thread_sync;" ::: "memory");
    if (tid < 128) {
        float* Crow = g_mapped + (m0 + tid) * DIM;
#pragma unroll
        for (int j = 0; j < 8; j++) {
            uint32_t r[32];
            LDTM_X32(r, tb + j * 32);
            asm volatile("tcgen05.wait::ld.sync.aligned;" ::: "memory");
#pragma unroll
            for (int q = 0; q < 8; q++) {
                float4 v = make_float4(__uint_as_float(r[q * 4 + 0]),
                                       __uint_as_float(r[q * 4 + 1]),
                                       __uint_as_float(r[q * 4 + 2]),
                                       __uint_as_float(r[q * 4 + 3]));
                *(float4*)(Crow + j * 32 + q * 4) = v;
            }
        }
    }
    __syncthreads();
    if (wid == 0) {
        asm volatile("tcgen05.dealloc.cta_group::1.sync.aligned.b32 %0, %1;"
                     :: "r"(tb), "r"(256u));
    }
#else
    size_t m0 = (size_t)blockIdx.x * 128;
    int tid = threadIdx.x;
    for (int e = tid; e < 128 * 256; e += 256) {
        int r = e >> 8, n = e & 255;
        float acc = 0.f;
        for (int k = 0; k < DIM; k++)
            acc += A[(m0 + r) * DIM + k] * W[k * DIM + n];
        g_mapped[(m0 + r) * DIM + n] = acc;
    }
#endif
}

// ---------------- fused capsule iteration: CTA per batch ------------------
// softmax + Z + squash + delta in one kernel; the delta re-read of mapped_b
// hits L2 (per-CTA 205 KB streamed moments earlier). Warp owns 4 capsules in
// the delta phase (32 caps regs, 6-shfl reduction).
__global__ __launch_bounds__(256, 3) void k_capsule(const int* __restrict__ seq_len,
                                                    float* __restrict__ out,
                                                    int do_delta) {
    __shared__ __align__(16) float sm_w[SEQL * NCAPS];   // 6.4 KB, l-major
    __shared__ __align__(16) float sm_caps[NCAPS * DIM]; // 8 KB
    __shared__ float sm_red[64];
    __shared__ float sm_sc[8];

    int b = blockIdx.x;
    int tid = threadIdx.x;
    int warp = tid >> 5, lane = tid & 31;
    int seq = seq_len[b];

    // ---- masked softmax over l for capsule k = warp ----
    {
        int k = warp;
        float vals[7];
        float mx = -INFINITY;
#pragma unroll
        for (int j = 0; j < 7; j++) {
            int l = lane + 32 * j;
            float v = (l < seq) ? g_logits[k * SEQL + l] : -INFINITY;
            vals[j] = v;
            mx = fmaxf(mx, v);
        }
#pragma unroll
        for (int off = 16; off; off >>= 1)
            mx = fmaxf(mx, __shfl_xor_sync(0xffffffffu, mx, off));
        float s = 0.f;
#pragma unroll
        for (int j = 0; j < 7; j++) {
            float e = expf(vals[j] - mx);
            vals[j] = e;
            s += e;
        }
#pragma unroll
        for (int off = 16; off; off >>= 1)
            s += __shfl_xor_sync(0xffffffffu, s, off);
        float inv = 1.f / s;
#pragma unroll
        for (int j = 0; j < 7; j++) {
            int l = lane + 32 * j;
            if (l < SEQL) sm_w[l * NCAPS + k] = vals[j] * inv;
        }
    }
    __syncthreads();

    const float* __restrict__ mb = g_mapped + (size_t)b * (SEQL * DIM);

    // ---- Z[k][o] = sum_l w[k][l]*m[l][o]; thread owns o, unroll-8 ----
    int o = tid;
    ull z2[4] = {0ULL, 0ULL, 0ULL, 0ULL};
    int l = 0;
    for (; l + 8 <= seq; l += 8) {
        float mm[8];
#pragma unroll
        for (int j = 0; j < 8; j++)
            mm[j] = mb[(size_t)(l + j) * DIM + o];
#pragma unroll
        for (int j = 0; j < 8; j++) {
            ull md = dup2(mm[j]);
            ulonglong2 wa = *(const ulonglong2*)&sm_w[(l + j) * NCAPS];
            ulonglong2 wb = *(const ulonglong2*)&sm_w[(l + j) * NCAPS + 4];
            z2[0] = ffma2(md, wa.x, z2[0]);
            z2[1] = ffma2(md, wa.y, z2[1]);
            z2[2] = ffma2(md, wb.x, z2[2]);
            z2[3] = ffma2(md, wb.y, z2[3]);
        }
    }
    for (; l < seq; l++) {
        ull md = dup2(mb[(size_t)l * DIM + o]);
        ulonglong2 wa = *(const ulonglong2*)&sm_w[l * NCAPS];
        ulonglong2 wb = *(const ulonglong2*)&sm_w[l * NCAPS + 4];
        z2[0] = ffma2(md, wa.x, z2[0]);
        z2[1] = ffma2(md, wa.y, z2[1]);
        z2[2] = ffma2(md, wb.x, z2[2]);
        z2[3] = ffma2(md, wb.y, z2[3]);
    }
    float z[8];
    {
        float2 f;
        f = unpack2(z2[0]); z[0] = f.x; z[1] = f.y;
        f = unpack2(z2[1]); z[2] = f.x; z[3] = f.y;
        f = unpack2(z2[2]); z[4] = f.x; z[5] = f.y;
        f = unpack2(z2[3]); z[6] = f.x; z[7] = f.y;
    }

    // ---- squash ----
    {
        float zs[8];
#pragma unroll
        for (int k = 0; k < 8; k++) zs[k] = z[k] * z[k];
#pragma unroll
        for (int off = 16; off; off >>= 1)
#pragma unroll
            for (int k = 0; k < 8; k++)
                zs[k] += __shfl_xor_sync(0xffffffffu, zs[k], off);
        if (lane == 0) {
#pragma unroll
            for (int k = 0; k < 8; k++) sm_red[k * 8 + warp] = zs[k];
        }
    }
    __syncthreads();
    if (tid < 8) {
        float sq = 0.f;
#pragma unroll
        for (int w = 0; w < 8; w++) sq += sm_red[tid * 8 + w];
        sm_sc[tid] = sq / (1.f + sq) / sqrtf(sq + 1e-8f);
    }
    __syncthreads();

    // ---- capsules = scale * Z; write out (+ SMEM for delta phase) ----
#pragma unroll
    for (int k = 0; k < 8; k++) {
        float c = sm_sc[k] * z[k];
        sm_caps[k * DIM + o] = c;
        out[((size_t)b * NCAPS + k) * DIM + o] = c;
    }

    if (!do_delta) return;
    __syncthreads();

    // ---- delta phase: warp owns 4 capsules, l-stripe (warp&3)::4 ----
    {
        int kbase = (warp >> 2) * 4;
        int lphase = warp & 3;

        float4 c0[4], c1[4];
#pragma unroll
        for (int k = 0; k < 4; k++) {
            c0[k] = *(const float4*)&sm_caps[(kbase + k) * DIM + lane * 8];
            c1[k] = *(const float4*)&sm_caps[(kbase + k) * DIM + lane * 8 + 4];
        }

        bool writer = (lane & 7) == 0;
        int kw = kbase + ((lane >> 4) & 1) * 2 + ((lane >> 3) & 1);

        for (int ld = lphase; ld < SEQL; ld += 4) {
            float4 m0 = *(const float4*)&mb[(size_t)ld * DIM + lane * 8];
            float4 m1 = *(const float4*)&mb[(size_t)ld * DIM + lane * 8 + 4];
            float p[4];
#pragma unroll
            for (int k = 0; k < 4; k++) {
                p[k] = c0[k].x * m0.x + c0[k].y * m0.y + c0[k].z * m0.z + c0[k].w * m0.w
                     + c1[k].x * m1.x + c1[k].y * m1.y + c1[k].z * m1.z + c1[k].w * m1.w;
            }
            bool hi4 = (lane & 16) != 0;
            float t0 = hi4 ? p[0] : p[2];
            float t1 = hi4 ? p[1] : p[3];
            t0 = __shfl_xor_sync(0xffffffffu, t0, 16);
            t1 = __shfl_xor_sync(0xffffffffu, t1, 16);
            float q0 = (hi4 ? p[2] : p[0]) + t0;
            float q1 = (hi4 ? p[3] : p[1]) + t1;
            bool hi3 = (lane & 8) != 0;
            float t = hi3 ? q0 : q1;
            t = __shfl_xor_sync(0xffffffffu, t, 8);
            float r = (hi3 ? q1 : q0) + t;
            r += __shfl_xor_sync(0xffffffffu, r, 4);
            r += __shfl_xor_sync(0xffffffffu, r, 2);
            r += __shfl_xor_sync(0xffffffffu, r, 1);
            if (writer)
                g_part[((size_t)kw * SEQL + ld) * NBATCH + b] = r;
        }
    }
}

// ---------------- deterministic batch-reduce of delta into logits --------
__global__ __launch_bounds__(256) void k_update() {
    __shared__ float red[256];
    int i = blockIdx.x;  // 0..1599
    const float4* row = (const float4*)(g_part + (size_t)i * NBATCH);
    float4 v = row[threadIdx.x];
    red[threadIdx.x] = v.x + v.y + v.z + v.w;
    __syncthreads();
#pragma unroll
    for (int st = 128; st; st >>= 1) {
        if (threadIdx.x < st) red[threadIdx.x] += red[threadIdx.x + st];
        __syncthreads();
    }
    if (threadIdx.x == 0) g_logits[i] += red[0];
}

// ---------------- launch --------------------------------------------------
extern "C" void kernel_launch(void* const* d_in, const int* in_sizes, int n_in,
                              void* d_out, int out_size) {
    const float* emb  = (const float*)d_in[0];
    const int*   seq  = (const int*)d_in[1];
    const float* rlog = (const float*)d_in[2];
    const float* W    = (const float*)d_in[3];
    float* out = (float*)d_out;

    cudaFuncSetAttribute(k_gemm_tc, cudaFuncAttributeMaxDynamicSharedMemorySize,
                         GSM_BYTES);

    k_init<<<(NCAPS * SEQL + 255) / 256, 256>>>(rlog);
    k_convW<<<DIM, DIM>>>(W);
    k_gemm_tc<<<(NBATCH * SEQL) / 128, 256, GSM_BYTES>>>(emb, W);

    for (int it = 0; it < 3; it++) {
        k_capsule<<<NBATCH, 256>>>(seq, out, (it < 2) ? 1 : 0);
        if (it < 2) k_update<<<NCAPS * SEQL, 256>>>();
    }
}

// round 8
// speedup vs baseline: 3.8425x; 1.2657x over previous
#include <cuda_runtime.h>
#include <cuda_bf16.h>
#include <math.h>
#include <stdint.h>

typedef unsigned long long ull;

#define NBATCH 1024
#define SEQL   200
#define DIM    256
#define NCAPS  8

// tcgen05 is arch-SPECIFIC: only legal on sm_103a/sm_100a compilation variants.
// The harness also runs a generic compute_103 PTX pass; give it a fallback.
// (cp.async.bulk / mbarrier are sm_90 BASELINE features - no guard needed.)
#if !defined(__CUDA_ARCH__) || defined(__CUDA_ARCH_FEAT_SM103_ALL) || \
    defined(__CUDA_ARCH_FEAT_SM100_ALL) || defined(__CUDA_ARCH_FEAT_SM101_ALL)
#define TC_OK 1
#else
#define TC_OK 0
#endif

// ---------------- device scratch (no allocations allowed) ----------------
__device__ float g_mapped[(size_t)NBATCH * SEQL * DIM];   // 209.7 MB
__device__ float g_logits[NCAPS * SEQL];                  // 6.4 KB
__device__ float g_part[(size_t)NCAPS * SEQL * NBATCH];   // [k*L][b]
__device__ __nv_bfloat16 g_WhT[DIM * DIM];                // W^T hi split, [n][k]
__device__ __nv_bfloat16 g_WlT[DIM * DIM];                // W^T lo split, [n][k]

// ---------------- f32x2 helpers ------------------------------------------
__device__ __forceinline__ ull ffma2(ull a, ull b, ull c) {
    ull d;
    asm("fma.rn.f32x2 %0, %1, %2, %3;" : "=l"(d) : "l"(a), "l"(b), "l"(c));
    return d;
}
__device__ __forceinline__ ull dup2(float x) {
    ull d;
    asm("mov.b64 %0, {%1, %1};" : "=l"(d) : "f"(x));
    return d;
}
__device__ __forceinline__ float2 unpack2(ull a) {
    float2 f;
    asm("mov.b64 {%0, %1}, %2;" : "=f"(f.x), "=f"(f.y) : "l"(a));
    return f;
}

// ---------------- smem/mbarrier/TMA helpers (baseline PTX) ----------------
__device__ __forceinline__ uint32_t smem_u32(const void* p) {
    uint32_t a;
    asm("{ .reg .u64 t; cvta.to.shared.u64 t, %1; cvt.u32.u64 %0, t; }"
        : "=r"(a) : "l"(p));
    return a;
}
__device__ __forceinline__ void mbar_init(uint32_t a, uint32_t cnt) {
    asm volatile("mbarrier.init.shared.b64 [%0], %1;" :: "r"(a), "r"(cnt) : "memory");
}
__device__ __forceinline__ void mbar_expect_tx(uint32_t a, uint32_t bytes) {
    asm volatile("mbarrier.arrive.expect_tx.shared.b64 _, [%0], %1;"
                 :: "r"(a), "r"(bytes) : "memory");
}
__device__ __forceinline__ void tma_1d(uint32_t dst, const void* src,
                                       uint32_t bytes, uint32_t mbar) {
    asm volatile(
        "cp.async.bulk.shared::cluster.global.mbarrier::complete_tx::bytes "
        "[%0], [%1], %2, [%3];"
        :: "r"(dst), "l"(src), "r"(bytes), "r"(mbar) : "memory");
}
__device__ __forceinline__ void mbar_wait(uint32_t a, uint32_t par) {
    asm volatile(
        "{\n\t.reg .pred P;\n"
        "W%=:\n\t"
        "mbarrier.try_wait.parity.acquire.cta.shared::cta.b64 P, [%0], %1, 0x989680;\n\t"
        "@P bra D%=;\n\t"
        "bra W%=;\n"
        "D%=:\n\t}" :: "r"(a), "r"(par) : "memory");
}

#if TC_OK
__device__ __forceinline__ uint32_t elect1() {
    uint32_t p;
    asm volatile("{ .reg .pred p; elect.sync _|p, 0xFFFFFFFF; selp.b32 %0,1,0,p; }"
                 : "=r"(p));
    return p;
}
__device__ __forceinline__ void mma_f16_ss(uint32_t d, uint64_t a, uint64_t b,
                                           uint32_t id, uint32_t en) {
    asm volatile(
        "{\n\t.reg .pred p;\n\tsetp.ne.u32 p, %5, 0;\n\t"
        "tcgen05.mma.cta_group::1.kind::f16 [%0], %1, %2, %3, {%4,%4,%4,%4}, p;\n\t}"
        :: "r"(d), "l"(a), "l"(b), "r"(id), "r"(0u), "r"(en) : "memory");
}
#define LDTM_X32(r, addr) \
    asm volatile( \
        "tcgen05.ld.sync.aligned.32x32b.x32.b32 " \
        "{%0,%1,%2,%3,%4,%5,%6,%7,%8,%9,%10,%11,%12,%13,%14,%15," \
        "%16,%17,%18,%19,%20,%21,%22,%23,%24,%25,%26,%27,%28,%29,%30,%31}, [%32];" \
        : "=r"((r)[0]),"=r"((r)[1]),"=r"((r)[2]),"=r"((r)[3]), \
          "=r"((r)[4]),"=r"((r)[5]),"=r"((r)[6]),"=r"((r)[7]), \
          "=r"((r)[8]),"=r"((r)[9]),"=r"((r)[10]),"=r"((r)[11]), \
          "=r"((r)[12]),"=r"((r)[13]),"=r"((r)[14]),"=r"((r)[15]), \
          "=r"((r)[16]),"=r"((r)[17]),"=r"((r)[18]),"=r"((r)[19]), \
          "=r"((r)[20]),"=r"((r)[21]),"=r"((r)[22]),"=r"((r)[23]), \
          "=r"((r)[24]),"=r"((r)[25]),"=r"((r)[26]),"=r"((r)[27]), \
          "=r"((r)[28]),"=r"((r)[29]),"=r"((r)[30]),"=r"((r)[31]) \
        : "r"(addr))
#endif  // TC_OK

// ---------------- init kernels -------------------------------------------
__global__ void k_init(const float* __restrict__ rlog) {
    int i = blockIdx.x * blockDim.x + threadIdx.x;
    if (i < NCAPS * SEQL) g_logits[i] = rlog[i];
}

// split + transpose W: g_W*T[n][k] = split(W[k][n])
__global__ void k_convW(const float* __restrict__ W) {
    int k = blockIdx.x;
    int n = threadIdx.x;
    float v = W[k * DIM + n];
    __nv_bfloat16 h = __float2bfloat16(v);
    float r = v - __bfloat162float(h);
    g_WhT[n * DIM + k] = h;
    g_WlT[n * DIM + k] = __float2bfloat16(r);
}

// ---------------- tensor-core GEMM: g_mapped = A @ W ----------------------
#define OFF_AH 1024
#define OFF_AL 17408
#define OFF_BH 33792
#define OFF_BL 66560
#define GSM_BYTES 99328

__global__ __launch_bounds__(256, 2) void k_gemm_tc(const float* __restrict__ A,
                                                    const float* __restrict__ W) {
#if TC_OK
    extern __shared__ __align__(16) float sm[];
    char* sb = (char*)sm;
    uint32_t sbase = smem_u32(sm);
    int tid = threadIdx.x, wid = tid >> 5;
    size_t m0 = (size_t)blockIdx.x * 128;

    if (wid == 0) {
        asm volatile("tcgen05.alloc.cta_group::1.sync.aligned.shared::cta.b32 [%0], %1;"
                     :: "r"(sbase), "r"(256u) : "memory");
        asm volatile("tcgen05.relinquish_alloc_permit.cta_group::1.sync.aligned;");
    }
    __syncthreads();
    uint32_t tb;
    asm volatile("ld.shared.b32 %0, [%1];" : "=r"(tb) : "r"(sbase));

    if (tid == 0) mbar_init(sbase + 8, 1u);
    __syncthreads();

    const uint64_t DB = (2ULL << 61) | (1ULL << 46) | (64ULL << 32) | (1ULL << 16);
    uint64_t dAh = DB | (((uint64_t)(sbase + OFF_AH) >> 4) & 0x3FFF);
    uint64_t dAl = DB | (((uint64_t)(sbase + OFF_AL) >> 4) & 0x3FFF);
    uint64_t dBh = DB | (((uint64_t)(sbase + OFF_BH) >> 4) & 0x3FFF);
    uint64_t dBl = DB | (((uint64_t)(sbase + OFF_BL) >> 4) & 0x3FFF);
    const uint32_t idesc = (1u << 4) | (1u << 7) | (1u << 10) |
                           ((DIM / 8) << 17) | ((128 / 16) << 24);

    float4 fA[8];
#pragma unroll
    for (int i = 0; i < 8; i++) {
        int idx = tid + i * 256;
        int r = idx >> 4, c4 = idx & 15;
        fA[i] = *(const float4*)(A + (m0 + r) * DIM + 0 + c4 * 4);
    }

    uint32_t first = 0;
    for (int c = 0; c < 4; c++) {
        int k0 = c * 64;
#pragma unroll
        for (int i = 0; i < 8; i++) {
            int idx = tid + i * 256;
            int r = idx >> 4, c4 = idx & 15;
            float4 f = fA[i];
            __nv_bfloat16 h0 = __float2bfloat16(f.x), h1 = __float2bfloat16(f.y),
                          h2 = __float2bfloat16(f.z), h3 = __float2bfloat16(f.w);
            float l0 = f.x - __bfloat162float(h0), l1 = f.y - __bfloat162float(h1),
                  l2 = f.z - __bfloat162float(h2), l3 = f.w - __bfloat162float(h3);
            uint32_t off = r * 128 + c4 * 8;
            uint32_t sw = off ^ ((off >> 3) & 0x70);
            uint2 uh, ulv;
            uh.x = ((uint32_t)__bfloat16_as_ushort(h1) << 16) | __bfloat16_as_ushort(h0);
            uh.y = ((uint32_t)__bfloat16_as_ushort(h3) << 16) | __bfloat16_as_ushort(h2);
            __nv_bfloat16 q0 = __float2bfloat16(l0), q1 = __float2bfloat16(l1),
                          q2 = __float2bfloat16(l2), q3 = __float2bfloat16(l3);
            ulv.x = ((uint32_t)__bfloat16_as_ushort(q1) << 16) | __bfloat16_as_ushort(q0);
            ulv.y = ((uint32_t)__bfloat16_as_ushort(q3) << 16) | __bfloat16_as_ushort(q2);
            *(uint2*)(sb + OFF_AH + sw) = uh;
            *(uint2*)(sb + OFF_AL + sw) = ulv;
        }
#pragma unroll
        for (int i = 0; i < 8; i++) {
            int idx = tid + i * 256;
            int r = idx >> 3, cc = idx & 7;
            uint32_t off = r * 128 + cc * 16;
            uint32_t sw = off ^ ((off >> 3) & 0x70);
            uint4 vh = *(const uint4*)((const char*)g_WhT + r * 512 + k0 * 2 + cc * 16);
            uint4 vl = *(const uint4*)((const char*)g_WlT + r * 512 + k0 * 2 + cc * 16);
            *(uint4*)(sb + OFF_BH + sw) = vh;
            *(uint4*)(sb + OFF_BL + sw) = vl;
        }
        __syncthreads();
        if (wid == 0) {
            asm volatile("fence.proxy.async.shared::cta;" ::: "memory");
            if (elect1()) {
#pragma unroll
                for (int s = 0; s < 4; s++) {
                    mma_f16_ss(tb, dAh + s * 2, dBh + s * 2, idesc, first);
                    first = 1;
                    mma_f16_ss(tb, dAh + s * 2, dBl + s * 2, idesc, 1);
                    mma_f16_ss(tb, dAl + s * 2, dBh + s * 2, idesc, 1);
                }
                asm volatile(
                    "tcgen05.commit.cta_group::1.mbarrier::arrive::one.shared::cluster.b64 [%0];"
                    :: "r"(sbase + 8) : "memory");
            }
        }
        if (c < 3) {
            int kn = k0 + 64;
#pragma unroll
            for (int i = 0; i < 8; i++) {
                int idx = tid + i * 256;
                int r = idx >> 4, c4 = idx & 15;
                fA[i] = *(const float4*)(A + (m0 + r) * DIM + kn + c4 * 4);
            }
        }
        mbar_wait(sbase + 8, (uint32_t)(c & 1));
    }

    asm volatile("tcgen05.fence::after_thread_sync;" ::: "memory");
    if (tid < 128) {
        float* Crow = g_mapped + (m0 + tid) * DIM;
#pragma unroll
        for (int j = 0; j < 8; j++) {
            uint32_t r[32];
            LDTM_X32(r, tb + j * 32);
            asm volatile("tcgen05.wait::ld.sync.aligned;" ::: "memory");
#pragma unroll
            for (int q = 0; q < 8; q++) {
                float4 v = make_float4(__uint_as_float(r[q * 4 + 0]),
                                       __uint_as_float(r[q * 4 + 1]),
                                       __uint_as_float(r[q * 4 + 2]),
                                       __uint_as_float(r[q * 4 + 3]));
                *(float4*)(Crow + j * 32 + q * 4) = v;
            }
        }
    }
    __syncthreads();
    if (wid == 0) {
        asm volatile("tcgen05.dealloc.cta_group::1.sync.aligned.b32 %0, %1;"
                     :: "r"(tb), "r"(256u));
    }
#else
    size_t m0 = (size_t)blockIdx.x * 128;
    int tid = threadIdx.x;
    for (int e = tid; e < 128 * 256; e += 256) {
        int r = e >> 8, n = e & 255;
        float acc = 0.f;
        for (int k = 0; k < DIM; k++)
            acc += A[(m0 + r) * DIM + k] * W[k * DIM + n];
        g_mapped[(m0 + r) * DIM + n] = acc;
    }
#endif
}

// ---------------- k_caps: softmax + Z + squash with TMA ring --------------
// 4-stage x 16-row (16 KB) SMEM ring fed by cp.async.bulk; compute from SMEM.
// byte layout: [0,32) mbars | [128, 65664) ring | [65664, 72064) weights |
//              [72064,..) red/sc
#define CAPS_SM_BYTES 72448

__global__ __launch_bounds__(256, 3) void k_caps(const int* __restrict__ seq_len,
                                                 float* __restrict__ out) {
    extern __shared__ __align__(16) char dsm[];
    uint32_t sbase = smem_u32(dsm);
    float* ring   = (float*)(dsm + 128);
    float* sm_w   = (float*)(dsm + 65664);
    float* sm_red = (float*)(dsm + 72064);
    float* sm_sc  = (float*)(dsm + 72320);

    int b = blockIdx.x;
    int tid = threadIdx.x;
    int warp = tid >> 5, lane = tid & 31;
    int seq = seq_len[b];
    int nblk = (seq + 15) >> 4;
    const float* __restrict__ mbp = g_mapped + (size_t)b * (SEQL * DIM);

    if (tid == 0) {
#pragma unroll
        for (int s = 0; s < 4; s++) mbar_init(sbase + s * 8, 1u);
    }
    __syncthreads();
    if (tid == 0) {
        int pre = nblk < 3 ? nblk : 3;
        for (int s = 0; s < pre; s++) {
            int rows = seq - s * 16; if (rows > 16) rows = 16;
            uint32_t bytes = (uint32_t)rows * 1024u;
            mbar_expect_tx(sbase + s * 8, bytes);
            tma_1d(sbase + 128 + s * 16384, mbp + (size_t)s * 16 * 256, bytes,
                   sbase + s * 8);
        }
    }

    // ---- masked softmax over l for capsule k = warp (overlaps TMA) ----
    {
        int k = warp;
        float vals[7];
        float mx = -INFINITY;
#pragma unroll
        for (int j = 0; j < 7; j++) {
            int l = lane + 32 * j;
            float v = (l < seq) ? g_logits[k * SEQL + l] : -INFINITY;
            vals[j] = v;
            mx = fmaxf(mx, v);
        }
#pragma unroll
        for (int off = 16; off; off >>= 1)
            mx = fmaxf(mx, __shfl_xor_sync(0xffffffffu, mx, off));
        float s = 0.f;
#pragma unroll
        for (int j = 0; j < 7; j++) {
            float e = expf(vals[j] - mx);
            vals[j] = e;
            s += e;
        }
#pragma unroll
        for (int off = 16; off; off >>= 1)
            s += __shfl_xor_sync(0xffffffffu, s, off);
        float inv = 1.f / s;
#pragma unroll
        for (int j = 0; j < 7; j++) {
            int l = lane + 32 * j;
            if (l < SEQL) sm_w[l * NCAPS + k] = vals[j] * inv;
        }
    }
    __syncthreads();

    // ---- Z from SMEM ring ----
    ull z2[4] = {0ULL, 0ULL, 0ULL, 0ULL};
    for (int blk = 0; blk < nblk; blk++) {
        mbar_wait(sbase + (blk & 3) * 8, (uint32_t)((blk >> 2) & 1));
        const float* st = ring + (blk & 3) * 4096;
        int base = blk * 16;
        int rows = seq - base; if (rows > 16) rows = 16;
        if (rows == 16) {
#pragma unroll
            for (int r = 0; r < 16; r++) {
                ull md = dup2(st[r * 256 + tid]);
                ulonglong2 wa = *(const ulonglong2*)&sm_w[(base + r) * NCAPS];
                ulonglong2 wb = *(const ulonglong2*)&sm_w[(base + r) * NCAPS + 4];
                z2[0] = ffma2(md, wa.x, z2[0]);
                z2[1] = ffma2(md, wa.y, z2[1]);
                z2[2] = ffma2(md, wb.x, z2[2]);
                z2[3] = ffma2(md, wb.y, z2[3]);
            }
        } else {
            for (int r = 0; r < rows; r++) {
                ull md = dup2(st[r * 256 + tid]);
                ulonglong2 wa = *(const ulonglong2*)&sm_w[(base + r) * NCAPS];
                ulonglong2 wb = *(const ulonglong2*)&sm_w[(base + r) * NCAPS + 4];
                z2[0] = ffma2(md, wa.x, z2[0]);
                z2[1] = ffma2(md, wa.y, z2[1]);
                z2[2] = ffma2(md, wb.x, z2[2]);
                z2[3] = ffma2(md, wb.y, z2[3]);
            }
        }
        __syncthreads();   // all threads done with this stage before reissue
        int nb = blk + 3;
        if (tid == 0 && nb < nblk) {
            int rows2 = seq - nb * 16; if (rows2 > 16) rows2 = 16;
            uint32_t bytes = (uint32_t)rows2 * 1024u;
            mbar_expect_tx(sbase + (nb & 3) * 8, bytes);
            tma_1d(sbase + 128 + (nb & 3) * 16384, mbp + (size_t)nb * 16 * 256,
                   bytes, sbase + (nb & 3) * 8);
        }
    }

    float z[8];
    {
        float2 f;
        f = unpack2(z2[0]); z[0] = f.x; z[1] = f.y;
        f = unpack2(z2[1]); z[2] = f.x; z[3] = f.y;
        f = unpack2(z2[2]); z[4] = f.x; z[5] = f.y;
        f = unpack2(z2[3]); z[6] = f.x; z[7] = f.y;
    }

    // ---- squash ----
    {
        float zs[8];
#pragma unroll
        for (int k = 0; k < 8; k++) zs[k] = z[k] * z[k];
#pragma unroll
        for (int off = 16; off; off >>= 1)
#pragma unroll
            for (int k = 0; k < 8; k++)
                zs[k] += __shfl_xor_sync(0xffffffffu, zs[k], off);
        if (lane == 0) {
#pragma unroll
            for (int k = 0; k < 8; k++) sm_red[k * 8 + warp] = zs[k];
        }
    }
    __syncthreads();
    if (tid < 8) {
        float sq = 0.f;
#pragma unroll
        for (int w = 0; w < 8; w++) sq += sm_red[tid * 8 + w];
        sm_sc[tid] = sq / (1.f + sq) / sqrtf(sq + 1e-8f);
    }
    __syncthreads();

#pragma unroll
    for (int k = 0; k < 8; k++)
        out[((size_t)b * NCAPS + k) * DIM + tid] = sm_sc[k] * z[k];
}

// ---------------- k_delta: TMA-streamed delta partials --------------------
// Same ring; all 200 rows. Warp owns 4 capsules (f32x2 dots), l-stripe mod 4.
#define DELTA_SM_BYTES 65792
#define DNBLK 13  // 12 x 16 + 1 x 8

__global__ __launch_bounds__(256, 3) void k_delta(const float* __restrict__ caps) {
    extern __shared__ __align__(16) char dsm[];
    uint32_t sbase = smem_u32(dsm);
    float* ring = (float*)(dsm + 128);

    int b = blockIdx.x;
    int tid = threadIdx.x;
    int warp = tid >> 5, lane = tid & 31;
    int kbase = (warp >> 2) * 4;
    int lphase = warp & 3;
    const float* __restrict__ mbp = g_mapped + (size_t)b * (SEQL * DIM);
    const float* __restrict__ cb = caps + (size_t)b * (NCAPS * DIM);

    if (tid == 0) {
#pragma unroll
        for (int s = 0; s < 4; s++) mbar_init(sbase + s * 8, 1u);
    }
    __syncthreads();
    if (tid == 0) {
        for (int s = 0; s < 3; s++) {
            uint32_t bytes = 16 * 1024u;
            mbar_expect_tx(sbase + s * 8, bytes);
            tma_1d(sbase + 128 + s * 16384, mbp + (size_t)s * 16 * 256, bytes,
                   sbase + s * 8);
        }
    }

    // caps for 4 owned capsules as f32x2 pairs (loads overlap TMA)
    ull c2[4][4];
#pragma unroll
    for (int k = 0; k < 4; k++) {
        ulonglong2 ca = *(const ulonglong2*)&cb[(kbase + k) * DIM + lane * 8];
        ulonglong2 cv = *(const ulonglong2*)&cb[(kbase + k) * DIM + lane * 8 + 4];
        c2[k][0] = ca.x; c2[k][1] = ca.y; c2[k][2] = cv.x; c2[k][3] = cv.y;
    }

    bool writer = (lane & 7) == 0;
    int kw = kbase + ((lane >> 4) & 1) * 2 + ((lane >> 3) & 1);

    for (int blk = 0; blk < DNBLK; blk++) {
        mbar_wait(sbase + (blk & 3) * 8, (uint32_t)((blk >> 2) & 1));
        const float* st = ring + (blk & 3) * 4096;
        int base = blk * 16;
        int rcnt = SEQL - base; if (rcnt > 16) rcnt = 16;
#pragma unroll
        for (int r0 = 0; r0 < 16; r0 += 4) {
            int r = r0 + lphase;
            if (r >= rcnt) break;
            ulonglong2 m0 = *(const ulonglong2*)&st[r * 256 + lane * 8];
            ulonglong2 m1 = *(const ulonglong2*)&st[r * 256 + lane * 8 + 4];
            float p[4];
#pragma unroll
            for (int k = 0; k < 4; k++) {
                ull acc = 0ULL;
                acc = ffma2(c2[k][0], m0.x, acc);
                acc = ffma2(c2[k][1], m0.y, acc);
                acc = ffma2(c2[k][2], m1.x, acc);
                acc = ffma2(c2[k][3], m1.y, acc);
                float2 f = unpack2(acc);
                p[k] = f.x + f.y;
            }
            bool hi4 = (lane & 16) != 0;
            float t0 = hi4 ? p[0] : p[2];
            float t1 = hi4 ? p[1] : p[3];
            t0 = __shfl_xor_sync(0xffffffffu, t0, 16);
            t1 = __shfl_xor_sync(0xffffffffu, t1, 16);
            float q0 = (hi4 ? p[2] : p[0]) + t0;
            float q1 = (hi4 ? p[3] : p[1]) + t1;
            bool hi3 = (lane & 8) != 0;
            float t = hi3 ? q0 : q1;
            t = __shfl_xor_sync(0xffffffffu, t, 8);
            float rr = (hi3 ? q1 : q0) + t;
            rr += __shfl_xor_sync(0xffffffffu, rr, 4);
            rr += __shfl_xor_sync(0xffffffffu, rr, 2);
            rr += __shfl_xor_sync(0xffffffffu, rr, 1);
            if (writer)
                g_part[((size_t)kw * SEQL + base + r) * NBATCH + b] = rr;
        }
        __syncthreads();
        int nb = blk + 3;
        if (tid == 0 && nb < DNBLK) {
            int rows2 = SEQL - nb * 16; if (rows2 > 16) rows2 = 16;
            uint32_t bytes = (uint32_t)rows2 * 1024u;
            mbar_expect_tx(sbase + (nb & 3) * 8, bytes);
            tma_1d(sbase + 128 + (nb & 3) * 16384, mbp + (size_t)nb * 16 * 256,
                   bytes, sbase + (nb & 3) * 8);
        }
    }
}

// ---------------- deterministic batch-reduce of delta into logits --------
__global__ __launch_bounds__(256) void k_update() {
    __shared__ float red[256];
    int i = blockIdx.x;  // 0..1599
    const float4* row = (const float4*)(g_part + (size_t)i * NBATCH);
    float4 v = row[threadIdx.x];
    red[threadIdx.x] = v.x + v.y + v.z + v.w;
    __syncthreads();
#pragma unroll
    for (int st = 128; st; st >>= 1) {
        if (threadIdx.x < st) red[threadIdx.x] += red[threadIdx.x + st];
        __syncthreads();
    }
    if (threadIdx.x == 0) g_logits[i] += red[0];
}

// ---------------- launch --------------------------------------------------
extern "C" void kernel_launch(void* const* d_in, const int* in_sizes, int n_in,
                              void* d_out, int out_size) {
    const float* emb  = (const float*)d_in[0];
    const int*   seq  = (const int*)d_in[1];
    const float* rlog = (const float*)d_in[2];
    const float* W    = (const float*)d_in[3];
    float* out = (float*)d_out;

    cudaFuncSetAttribute(k_gemm_tc, cudaFuncAttributeMaxDynamicSharedMemorySize,
                         GSM_BYTES);
    cudaFuncSetAttribute(k_caps, cudaFuncAttributeMaxDynamicSharedMemorySize,
                         CAPS_SM_BYTES);
    cudaFuncSetAttribute(k_delta, cudaFuncAttributeMaxDynamicSharedMemorySize,
                         DELTA_SM_BYTES);

    k_init<<<(NCAPS * SEQL + 255) / 256, 256>>>(rlog);
    k_convW<<<DIM, DIM>>>(W);
    k_gemm_tc<<<(NBATCH * SEQL) / 128, 256, GSM_BYTES>>>(emb, W);

    for (int it = 0; it < 3; it++) {
        k_caps<<<NBATCH, 256, CAPS_SM_BYTES>>>(seq, out);
        if (it < 2) {
            k_delta<<<NBATCH, 256, DELTA_SM_BYTES>>>(out);
            k_update<<<NCAPS * SEQL, 256>>>();
        }
    }
}